// round 14
// baseline (speedup 1.0000x reference)
#include <cuda_runtime.h>
#include <cuda_bf16.h>
#include <math.h>
#include <stdint.h>

#define SQ   4096
#define EMB  300
#define NH   3
#define HDIM 100
#define NHID 200
#define QB   64
#define TJ   32
#define JCH  1024
#define NCH  4
#define KSPL 1024
#define ASTR 136
#define BSTR 72
#define QKVS 468   // padded qkv row stride (words): 3 segs x 156, head stride 52
#define VSTR 136   // v_s d-stride (64-bit units): tig*136 mod 32 = 8*tig -> conflict-free LDS.64

// ---------------- scratch ----------------
__device__ float g_x[2 * SQ * EMB];
__device__ uint32_t g_xb[2 * SQ * 150];
__device__ uint32_t g_xbT[2 * EMB * (SQ / 2)];
__device__ uint32_t g_wpack[480000];
__device__ __align__(16) uint32_t g_qkvb[2 * SQ * QKVS];
__device__ uint32_t g_ob[2 * SQ * 150];
__device__ float g_t1[2 * SQ * EMB];
__device__ uint32_t g_ffb[2 * SQ * 100];
__device__ float g_A[SQ * SQ];
__device__ __nv_bfloat16 g_Ab[SQ * SQ];
__device__ float g_P[SQ * EMB];
__device__ float g_Q[SQ * EMB];
__device__ float g_Pp[NCH * SQ * EMB];
__device__ float g_Qp[NCH * SQ * EMB];
__device__ float g_part_o[6 * NCH * SQ * HDIM];
__device__ float g_part_ml[6 * NCH * SQ * 2];
__device__ float g_colpart[2 * 32 * EMB];
__device__ float g_suv[2 * EMB];
__device__ float g_fc1o[EMB];

// ---------------- bf16 helpers ----------------
__device__ __forceinline__ uint32_t packbf(float lo, float hi) {
    uint32_t r;
    asm("cvt.rn.bf16x2.f32 %0, %1, %2;" : "=r"(r) : "f"(hi), "f"(lo));
    return r;
}

#define MMA_BF16(C, A, B0, B1)                                                  \
    asm volatile(                                                               \
        "mma.sync.aligned.m16n8k16.row.col.f32.bf16.bf16.f32 "                  \
        "{%0,%1,%2,%3},{%4,%5,%6,%7},{%8,%9},{%0,%1,%2,%3};"                    \
        : "+f"((C)[0]), "+f"((C)[1]), "+f"((C)[2]), "+f"((C)[3])                \
        : "r"((A)[0]), "r"((A)[1]), "r"((A)[2]), "r"((A)[3]), "r"(B0), "r"(B1))

#define LDMX4(R, ADDR)                                                          \
    asm volatile("ldmatrix.sync.aligned.m8n8.x4.shared.b16 {%0,%1,%2,%3}, [%4];" \
        : "=r"((R)[0]), "=r"((R)[1]), "=r"((R)[2]), "=r"((R)[3]) : "r"(ADDR))

// ---------------- packing kernels ----------------
__global__ void pack4(const float* __restrict__ ipw, const float* __restrict__ ow,
                      const float* __restrict__ w1, const float* __restrict__ w2,
                      uint32_t* __restrict__ dst) {
    int i = blockIdx.x * 256 + threadIdx.x;
    if (i >= 480000) return;
    const float* src;
    int off;
    if (i < 270000)      { src = ipw; off = i; }
    else if (i < 360000) { src = ow;  off = i - 270000; }
    else if (i < 420000) { src = w1;  off = i - 360000; }
    else                 { src = w2;  off = i - 420000; }
    float2 v = ((const float2*)src)[off];
    dst[i] = packbf(v.x, v.y);
}

__global__ void transpose_pack(const float* __restrict__ x, uint32_t* __restrict__ xT) {
    __shared__ float tile[64][65];
    int z = blockIdx.z;
    int s0 = blockIdx.x * 64, c0 = blockIdx.y * 64;
    int t = threadIdx.x;
#pragma unroll
    for (int i = 0; i < 16; i++) {
        int idx = t + i * 256;
        int ls = idx >> 6, lc = idx & 63;
        int c = c0 + lc;
        tile[ls][lc] = (c < EMB) ? x[(size_t)z * SQ * EMB + (size_t)(s0 + ls) * EMB + c] : 0.f;
    }
    __syncthreads();
#pragma unroll
    for (int i = 0; i < 8; i++) {
        int idx = t + i * 256;
        int lc = idx >> 5, lsp = idx & 31;
        int c = c0 + lc;
        if (c < EMB)
            xT[(size_t)z * EMB * (SQ / 2) + (size_t)c * (SQ / 2) + (s0 >> 1) + lsp] =
                packbf(tile[2 * lsp][lc], tile[2 * lsp + 1][lc]);
    }
}

// ---------------- positional encoding + add ----------------
__global__ void add_pe_kernel(const float* __restrict__ solv, const float* __restrict__ solu,
                              float* __restrict__ x, uint32_t* __restrict__ xb) {
    int p = blockIdx.x * blockDim.x + threadIdx.x;
    if (p >= SQ * 150) return;
    int z = blockIdx.z;
    const float* src = z ? solu : solv;
    int s = p / 150, pc = p - s * 150, c = 2 * pc;
    float dv = __expf(-(float)c * (logf(10000.0f) / (float)EMB));
    float arg = (float)s * dv;
    float pe0 = sinf(arg), pe1 = cosf(arg);
    float2 a = *(const float2*)&src[(size_t)s * EMB + c];
    float v0 = a.x + pe0, v1 = a.y + pe1;
    *(float2*)&x[(size_t)z * SQ * EMB + (size_t)s * EMB + c] = make_float2(v0, v1);
    xb[(size_t)z * SQ * 150 + p] = packbf(v0, v1);
}

// ---------------- all-bf16 tensor-core GEMM ----------------
template<int TA, int RELU, int SPLITK, int BF16OUT>
__global__ __launch_bounds__(256, 2)
void mma2(const __nv_bfloat16* __restrict__ A, const __nv_bfloat16* __restrict__ B,
          const float* __restrict__ bias, float* __restrict__ C,
          int M, int N, int K, int lda, int ldb,
          size_t sA, size_t sB, size_t sBias, size_t sC, int kc) {
    int z = blockIdx.z;
    int k_begin = 0, k_end = K;
    if (SPLITK) {
        k_begin = z * kc;
        k_end = min(K, k_begin + kc);
        C += (size_t)z * sC;
    } else {
        A += (size_t)z * sA; B += (size_t)z * sB; C += (size_t)z * sC;
        if (bias) bias += (size_t)z * sBias;
    }
    uint32_t* C32 = (uint32_t*)C;

    __shared__ uint32_t As[2][16][ASTR];
    __shared__ uint32_t Bs[2][16][BSTR];

    int t = threadIdx.x;
    int warp = t >> 5, lane = t & 31;
    int g = lane >> 2, tig = lane & 3;
    int wm = warp & 3, wn = warp >> 2;
    int row0 = blockIdx.y * 128, col0 = blockIdx.x * 64;
    int wr0 = wm * 32, wc0 = wn * 32;

    float acc[2][4][4];
#pragma unroll
    for (int i = 0; i < 2; i++)
#pragma unroll
        for (int j = 0; j < 4; j++)
#pragma unroll
            for (int h = 0; h < 4; h++) acc[i][j][h] = 0.f;

    uint32_t ra[8], rb[4];

    auto loadA = [&](int kt) {
        if (!TA) {
            int m = t >> 1, kq = (t & 1) * 16;
            const uint32_t* Ap = (const uint32_t*)(A + (size_t)(row0 + m) * lda + kt + kq);
            if (kt + kq + 15 < k_end) {
#pragma unroll
                for (int u = 0; u < 8; u++) ra[u] = Ap[u];
            } else {
                const unsigned short* A16 = (const unsigned short*)(A + (size_t)(row0 + m) * lda);
#pragma unroll
                for (int u = 0; u < 8; u++) {
                    int gk = kt + kq + 2 * u;
                    uint32_t lo = (gk < k_end) ? A16[gk] : 0;
                    uint32_t hi = (gk + 1 < k_end) ? A16[gk + 1] : 0;
                    ra[u] = lo | (hi << 16);
                }
            }
        } else {
            int kp = t >> 4, mq = (t & 15) * 8;
            int gk0 = kt + 2 * kp;
            bool ok0 = gk0 < k_end, ok1 = gk0 + 1 < k_end;
            const uint32_t* r0p = (const uint32_t*)(A + (size_t)gk0 * lda + row0 + mq);
            const uint32_t* r1p = (const uint32_t*)(A + (size_t)(gk0 + 1) * lda + row0 + mq);
            if (ok1) {
#pragma unroll
                for (int u = 0; u < 4; u++) {
                    uint32_t w0 = r0p[u], w1 = r1p[u];
                    ra[2 * u]     = __byte_perm(w0, w1, 0x5410);
                    ra[2 * u + 1] = __byte_perm(w0, w1, 0x7632);
                }
            } else {
#pragma unroll
                for (int u = 0; u < 4; u++) {
                    uint32_t w0 = ok0 ? r0p[u] : 0;
                    ra[2 * u]     = __byte_perm(w0, 0u, 0x5410);
                    ra[2 * u + 1] = __byte_perm(w0, 0u, 0x7632);
                }
            }
        }
    };
    auto loadB = [&](int kt) {
        int n = t >> 2, kq = (t & 3) * 8;
        int gn = col0 + n;
        bool okn = gn < N;
        const uint32_t* Bp = (const uint32_t*)(B + (size_t)gn * ldb + kt + kq);
        if (okn && kt + kq + 7 < k_end) {
#pragma unroll
            for (int u = 0; u < 4; u++) rb[u] = Bp[u];
        } else {
            const unsigned short* B16 = (const unsigned short*)(B + (size_t)gn * ldb);
#pragma unroll
            for (int u = 0; u < 4; u++) {
                int gk = kt + kq + 2 * u;
                uint32_t lo = (okn && gk < k_end) ? B16[gk] : 0;
                uint32_t hi = (okn && gk + 1 < k_end) ? B16[gk + 1] : 0;
                rb[u] = lo | (hi << 16);
            }
        }
    };
    auto storeA = [&](int bf) {
        if (!TA) {
            int m = t >> 1, kp0 = (t & 1) * 8;
#pragma unroll
            for (int u = 0; u < 8; u++) As[bf][kp0 + u][m] = ra[u];
        } else {
            int kp = t >> 4, mq = (t & 15) * 8;
#pragma unroll
            for (int u = 0; u < 8; u++) As[bf][kp][mq + u] = ra[u];
        }
    };
    auto storeB = [&](int bf) {
        int n = t >> 2, kp0 = (t & 3) * 4;
#pragma unroll
        for (int u = 0; u < 4; u++) Bs[bf][kp0 + u][n] = rb[u];
    };

    int nk = (k_end - k_begin + 31) >> 5;
    loadA(k_begin); loadB(k_begin);
    storeA(0); storeB(0);
    __syncthreads();

    int buf = 0;
    for (int it = 0; it < nk; it++) {
        if (it + 1 < nk) { loadA(k_begin + (it + 1) * 32); loadB(k_begin + (it + 1) * 32); }
#pragma unroll
        for (int ks = 0; ks < 16; ks += 8) {
            uint32_t a[2][4], b[4][2];
#pragma unroll
            for (int i = 0; i < 2; i++) {
                int mb = wr0 + i * 16;
                a[i][0] = As[buf][ks + tig][mb + g];
                a[i][1] = As[buf][ks + tig][mb + 8 + g];
                a[i][2] = As[buf][ks + tig + 4][mb + g];
                a[i][3] = As[buf][ks + tig + 4][mb + 8 + g];
            }
#pragma unroll
            for (int j = 0; j < 4; j++) {
                int nb = wc0 + j * 8;
                b[j][0] = Bs[buf][ks + tig][nb + g];
                b[j][1] = Bs[buf][ks + tig + 4][nb + g];
            }
#pragma unroll
            for (int i = 0; i < 2; i++)
#pragma unroll
                for (int j = 0; j < 4; j++)
                    MMA_BF16(acc[i][j], a[i], b[j][0], b[j][1]);
        }
        if (it + 1 < nk) {
            storeA(1 - buf); storeB(1 - buf);
            __syncthreads();
            buf ^= 1;
        }
    }

#pragma unroll
    for (int i = 0; i < 2; i++) {
        int r0 = row0 + wr0 + i * 16 + g;
#pragma unroll
        for (int j = 0; j < 4; j++) {
            int cc = col0 + wc0 + j * 8 + tig * 2;
#pragma unroll
            for (int h = 0; h < 2; h++) {
                int gr = r0 + h * 8;
                float v0 = acc[i][j][h * 2], v1 = acc[i][j][h * 2 + 1];
                if (!SPLITK && bias) {
                    if (cc < N) v0 += bias[cc];
                    if (cc + 1 < N) v1 += bias[cc + 1];
                }
                if (RELU) { v0 = fmaxf(v0, 0.f); v1 = fmaxf(v1, 0.f); }
                if (BF16OUT == 2) {
                    if (cc < N) {
                        int seg = cc / 300, rem = cc - seg * 300;
                        int hh = rem / 100, wi = rem - hh * 100;
                        C32[(size_t)gr * QKVS + seg * 156 + hh * 52 + (wi >> 1)] = packbf(v0, v1);
                    }
                } else if (BF16OUT == 1) {
                    if (cc < N)
                        C32[(size_t)gr * (N >> 1) + (cc >> 1)] = packbf(v0, v1);
                } else if (cc + 1 < N) {
                    *(float2*)&C[(size_t)gr * N + cc] = make_float2(v0, v1);
                } else if (cc < N) {
                    C[(size_t)gr * N + cc] = v0;
                }
            }
        }
    }
}

// ---------------- fused P+Q split-K GEMM ----------------
__global__ __launch_bounds__(256, 2)
void mma2_pq(const __nv_bfloat16* __restrict__ Ain, const __nv_bfloat16* __restrict__ BP,
             const __nv_bfloat16* __restrict__ BQ, float* __restrict__ CP,
             float* __restrict__ CQ) {
    int z = blockIdx.z;
    int ta = (z >= NCH) ? 1 : 0;
    int zz = ta ? z - NCH : z;
    int k_begin = zz * KSPL;
    const __nv_bfloat16* B = ta ? BQ : BP;
    float* C = (ta ? CQ : CP) + (size_t)zz * SQ * EMB;
    const int lda = SQ, ldb = SQ, N = EMB;

    __shared__ uint32_t As[2][16][ASTR];
    __shared__ uint32_t Bs[2][16][BSTR];

    int t = threadIdx.x;
    int warp = t >> 5, lane = t & 31;
    int g = lane >> 2, tig = lane & 3;
    int wm = warp & 3, wn = warp >> 2;
    int row0 = blockIdx.y * 128, col0 = blockIdx.x * 64;
    int wr0 = wm * 32, wc0 = wn * 32;

    float acc[2][4][4];
#pragma unroll
    for (int i = 0; i < 2; i++)
#pragma unroll
        for (int j = 0; j < 4; j++)
#pragma unroll
            for (int h = 0; h < 4; h++) acc[i][j][h] = 0.f;

    uint32_t ra[8], rb[4];

    auto loadA = [&](int kt) {
        if (!ta) {
            int m = t >> 1, kq = (t & 1) * 16;
            const uint32_t* Ap = (const uint32_t*)(Ain + (size_t)(row0 + m) * lda + kt + kq);
#pragma unroll
            for (int u = 0; u < 8; u++) ra[u] = Ap[u];
        } else {
            int kp = t >> 4, mq = (t & 15) * 8;
            int gk0 = kt + 2 * kp;
            const uint32_t* r0p = (const uint32_t*)(Ain + (size_t)gk0 * lda + row0 + mq);
            const uint32_t* r1p = (const uint32_t*)(Ain + (size_t)(gk0 + 1) * lda + row0 + mq);
#pragma unroll
            for (int u = 0; u < 4; u++) {
                uint32_t w0 = r0p[u], w1 = r1p[u];
                ra[2 * u]     = __byte_perm(w0, w1, 0x5410);
                ra[2 * u + 1] = __byte_perm(w0, w1, 0x7632);
            }
        }
    };
    auto loadB = [&](int kt) {
        int n = t >> 2, kq = (t & 3) * 8;
        int gn = col0 + n;
        if (gn < N) {
            const uint32_t* Bp = (const uint32_t*)(B + (size_t)gn * ldb + kt + kq);
#pragma unroll
            for (int u = 0; u < 4; u++) rb[u] = Bp[u];
        } else {
#pragma unroll
            for (int u = 0; u < 4; u++) rb[u] = 0u;
        }
    };
    auto storeA = [&](int bf) {
        if (!ta) {
            int m = t >> 1, kp0 = (t & 1) * 8;
#pragma unroll
            for (int u = 0; u < 8; u++) As[bf][kp0 + u][m] = ra[u];
        } else {
            int kp = t >> 4, mq = (t & 15) * 8;
#pragma unroll
            for (int u = 0; u < 8; u++) As[bf][kp][mq + u] = ra[u];
        }
    };
    auto storeB = [&](int bf) {
        int n = t >> 2, kp0 = (t & 3) * 4;
#pragma unroll
        for (int u = 0; u < 4; u++) Bs[bf][kp0 + u][n] = rb[u];
    };

    const int nk = KSPL >> 5;
    loadA(k_begin); loadB(k_begin);
    storeA(0); storeB(0);
    __syncthreads();

    int buf = 0;
    for (int it = 0; it < nk; it++) {
        if (it + 1 < nk) { loadA(k_begin + (it + 1) * 32); loadB(k_begin + (it + 1) * 32); }
#pragma unroll
        for (int ks = 0; ks < 16; ks += 8) {
            uint32_t a[2][4], b[4][2];
#pragma unroll
            for (int i = 0; i < 2; i++) {
                int mb = wr0 + i * 16;
                a[i][0] = As[buf][ks + tig][mb + g];
                a[i][1] = As[buf][ks + tig][mb + 8 + g];
                a[i][2] = As[buf][ks + tig + 4][mb + g];
                a[i][3] = As[buf][ks + tig + 4][mb + 8 + g];
            }
#pragma unroll
            for (int j = 0; j < 4; j++) {
                int nb = wc0 + j * 8;
                b[j][0] = Bs[buf][ks + tig][nb + g];
                b[j][1] = Bs[buf][ks + tig + 4][nb + g];
            }
#pragma unroll
            for (int i = 0; i < 2; i++)
#pragma unroll
                for (int j = 0; j < 4; j++)
                    MMA_BF16(acc[i][j], a[i], b[j][0], b[j][1]);
        }
        if (it + 1 < nk) {
            storeA(1 - buf); storeB(1 - buf);
            __syncthreads();
            buf ^= 1;
        }
    }

#pragma unroll
    for (int i = 0; i < 2; i++) {
        int r0 = row0 + wr0 + i * 16 + g;
#pragma unroll
        for (int j = 0; j < 4; j++) {
            int cc = col0 + wc0 + j * 8 + tig * 2;
#pragma unroll
            for (int h = 0; h < 2; h++) {
                int gr = r0 + h * 8;
                float v0 = acc[i][j][h * 2], v1 = acc[i][j][h * 2 + 1];
                if (cc + 1 < N) {
                    *(float2*)&C[(size_t)gr * N + cc] = make_float2(v0, v1);
                } else if (cc < N) {
                    C[(size_t)gr * N + cc] = v0;
                }
            }
        }
    }
}

// ---------------- split-K reduce ----------------
__global__ void reduce_pq(const float* __restrict__ Pp, const float* __restrict__ Qp,
                          float* __restrict__ P, float* __restrict__ Q) {
    int idx = blockIdx.x * 256 + threadIdx.x;
    if (idx >= SQ * EMB / 4) return;
    const float* src = blockIdx.y ? Qp : Pp;
    float* dst = blockIdx.y ? Q : P;
    float4 r = make_float4(0.f, 0.f, 0.f, 0.f);
#pragma unroll
    for (int c = 0; c < NCH; c++) {
        float4 a = ((const float4*)(src + (size_t)c * SQ * EMB))[idx];
        r.x += a.x; r.y += a.y; r.z += a.z; r.w += a.w;
    }
    ((float4*)dst)[idx] = r;
}

// ---------------- bf16 flash attention: LDS.64 V pairs + rescale skip ----------------
__global__ __launch_bounds__(128, 5)
void attn_mma_kernel(const uint32_t* __restrict__ qb_all,
                     float* __restrict__ part_o, float* __restrict__ part_ml) {
    __shared__ __align__(16) uint32_t k_s[TJ][60];
    __shared__ __align__(8)  uint32_t v_s[2][4][VSTR][2];  // [kh][tig][d][half]
    __shared__ __align__(16) uint32_t q_s[4][16][60];

    int z = blockIdx.z, e = z / 3, h = z % 3;
    int qt = (int)gridDim.x - 1 - (int)blockIdx.x;
    int q0 = qt * QB;
    int c = blockIdx.y, c0 = c * JCH;
    if (c0 > q0 + QB - 1) return;

    const uint32_t* qb = qb_all + (size_t)e * SQ * QKVS;
    int t = threadIdx.x, w = t >> 5, lane = t & 31;
    int g = lane >> 2, tig = lane & 3;

    int r0 = q0 + w * 16 + g;
    int r1 = r0 + 8;

    // stage Q fragments into smem once
    {
        const uint32_t* q0p = qb + (size_t)r0 * QKVS + h * 52;
        const uint32_t* q1p = qb + (size_t)r1 * QKVS + h * 52;
#pragma unroll
        for (int s = 0; s < 7; s++) {
            int dp0 = s * 8 + tig, dp1 = dp0 + 4;
            q_s[w][g][dp0]     = dp0 < 50 ? q0p[dp0] : 0u;
            q_s[w][g + 8][dp0] = dp0 < 50 ? q1p[dp0] : 0u;
            q_s[w][g][dp1]     = dp1 < 50 ? q0p[dp1] : 0u;
            q_s[w][g + 8][dp1] = dp1 < 50 ? q1p[dp1] : 0u;
        }
    }
    // zero pad columns once (K d 50-55; V d 100-103)
    for (int idx = t; idx < 32 * 6; idx += 128) k_s[idx / 6][50 + idx % 6] = 0u;
    if (t < 64) {
        int kh = t >> 5, tg = (t >> 3) & 3, d = 100 + ((t >> 1) & 3), hf = t & 1;
        v_s[kh][tg][d][hf] = 0u;
    }

    uint32_t kbase0, kbase1, qbase;
    {
        int tile = lane >> 3, row = lane & 7;
        int krow = (tile >> 1) * 8 + row;
        int kword = (tile & 1) * 4;
        kbase0 = (uint32_t)__cvta_generic_to_shared(&k_s[krow][kword]);
        kbase1 = (uint32_t)__cvta_generic_to_shared(&k_s[16 + krow][kword]);
        int qrow = ((tile & 1) ? 8 : 0) + row;
        int qword = (tile >> 1) * 4;
        qbase = (uint32_t)__cvta_generic_to_shared(&q_s[w][qrow][qword]);
    }

    float of[13][4];
#pragma unroll
    for (int nt = 0; nt < 13; nt++) { of[nt][0] = of[nt][1] = of[nt][2] = of[nt][3] = 0.f; }
    float m0 = -INFINITY, m1 = -INFINITY, l0 = 0.f, l1 = 0.f;

    int jend = min(c0 + JCH, q0 + QB);
    for (int jt = c0; jt < jend; jt += TJ) {
        // K stage: vectorized
        for (int idx = t; idx < 32 * 13; idx += 128) {
            int row = idx / 13, sl = idx - row * 13;
            const uint32_t* src = qb + (size_t)(jt + row) * QKVS + 156 + h * 52;
            if (sl < 12) {
                *(uint4*)&k_s[row][4 * sl] = *(const uint4*)(src + 4 * sl);
            } else {
                *(uint2*)&k_s[row][48] = *(const uint2*)(src + 48);
            }
        }
        // V stage: interleave two j rows -> fragment-pair layout
        for (int idx = t; idx < 16 * 13; idx += 128) {
            int jp = idx / 13, sl = idx - jp * 13;
            int kh = jp >> 3, wi = jp & 7;
            int tg = wi & 3, hf = wi >> 2;
            const uint32_t* s0p = qb + (size_t)(jt + 2 * jp) * QKVS + 312 + h * 52;
            const uint32_t* s1p = s0p + QKVS;
            if (sl < 12) {
                uint4 a = *(const uint4*)(s0p + 4 * sl);
                uint4 b = *(const uint4*)(s1p + 4 * sl);
                int d0 = 8 * sl;
                v_s[kh][tg][d0    ][hf] = __byte_perm(a.x, b.x, 0x5410);
                v_s[kh][tg][d0 + 1][hf] = __byte_perm(a.x, b.x, 0x7632);
                v_s[kh][tg][d0 + 2][hf] = __byte_perm(a.y, b.y, 0x5410);
                v_s[kh][tg][d0 + 3][hf] = __byte_perm(a.y, b.y, 0x7632);
                v_s[kh][tg][d0 + 4][hf] = __byte_perm(a.z, b.z, 0x5410);
                v_s[kh][tg][d0 + 5][hf] = __byte_perm(a.z, b.z, 0x7632);
                v_s[kh][tg][d0 + 6][hf] = __byte_perm(a.w, b.w, 0x5410);
                v_s[kh][tg][d0 + 7][hf] = __byte_perm(a.w, b.w, 0x7632);
            } else {
                uint2 a = *(const uint2*)(s0p + 48);
                uint2 b = *(const uint2*)(s1p + 48);
                v_s[kh][tg][96][hf] = __byte_perm(a.x, b.x, 0x5410);
                v_s[kh][tg][97][hf] = __byte_perm(a.x, b.x, 0x7632);
                v_s[kh][tg][98][hf] = __byte_perm(a.y, b.y, 0x5410);
                v_s[kh][tg][99][hf] = __byte_perm(a.y, b.y, 0x7632);
            }
        }
        __syncthreads();

        // S = Q K^T via ldmatrix fragments
        float sc[4][4];
#pragma unroll
        for (int nt = 0; nt < 4; nt++) { sc[nt][0] = sc[nt][1] = sc[nt][2] = sc[nt][3] = 0.f; }
#pragma unroll
        for (int s = 0; s < 7; s++) {
            uint32_t qa[4], kb0[4], kb1[4];
            LDMX4(qa, qbase + s * 32);
            LDMX4(kb0, kbase0 + s * 32);
            LDMX4(kb1, kbase1 + s * 32);
            MMA_BF16(sc[0], qa, kb0[0], kb0[1]);
            MMA_BF16(sc[1], qa, kb0[2], kb0[3]);
            MMA_BF16(sc[2], qa, kb1[0], kb1[1]);
            MMA_BF16(sc[3], qa, kb1[2], kb1[3]);
        }
#pragma unroll
        for (int nt = 0; nt < 4; nt++) {
            sc[nt][0] *= 0.1f; sc[nt][1] *= 0.1f; sc[nt][2] *= 0.1f; sc[nt][3] *= 0.1f;
        }

        if (jt + TJ > q0) {
#pragma unroll
            for (int nt = 0; nt < 4; nt++) {
                int jb = jt + nt * 8 + 2 * tig;
                if (jb > r0)     sc[nt][0] = -INFINITY;
                if (jb + 1 > r0) sc[nt][1] = -INFINITY;
                if (jb > r1)     sc[nt][2] = -INFINITY;
                if (jb + 1 > r1) sc[nt][3] = -INFINITY;
            }
        }

        float rm0 = -INFINITY, rm1 = -INFINITY;
#pragma unroll
        for (int nt = 0; nt < 4; nt++) {
            rm0 = fmaxf(rm0, fmaxf(sc[nt][0], sc[nt][1]));
            rm1 = fmaxf(rm1, fmaxf(sc[nt][2], sc[nt][3]));
        }
        rm0 = fmaxf(rm0, __shfl_xor_sync(0xffffffffu, rm0, 1));
        rm0 = fmaxf(rm0, __shfl_xor_sync(0xffffffffu, rm0, 2));
        rm1 = fmaxf(rm1, __shfl_xor_sync(0xffffffffu, rm1, 1));
        rm1 = fmaxf(rm1, __shfl_xor_sync(0xffffffffu, rm1, 2));
        float mn0 = fmaxf(m0, rm0), mn1 = fmaxf(m1, rm1);
        float s0 = __expf(m0 - mn0), s1 = __expf(m1 - mn1);

        uint32_t pp[4][2];
        float rs0 = 0.f, rs1 = 0.f;
#pragma unroll
        for (int nt = 0; nt < 4; nt++) {
            float p0 = __expf(sc[nt][0] - mn0);
            float p1 = __expf(sc[nt][1] - mn0);
            float p2 = __expf(sc[nt][2] - mn1);
            float p3 = __expf(sc[nt][3] - mn1);
            rs0 += p0 + p1;
            rs1 += p2 + p3;
            pp[nt][0] = packbf(p0, p1);
            pp[nt][1] = packbf(p2, p3);
        }
        rs0 += __shfl_xor_sync(0xffffffffu, rs0, 1);
        rs0 += __shfl_xor_sync(0xffffffffu, rs0, 2);
        rs1 += __shfl_xor_sync(0xffffffffu, rs1, 1);
        rs1 += __shfl_xor_sync(0xffffffffu, rs1, 2);
        l0 = l0 * s0 + rs0;
        l1 = l1 * s1 + rs1;
        m0 = mn0; m1 = mn1;

        // skip O-rescale when no lane saw a new max (x * 1.0f == x exactly)
        if (!__all_sync(0xffffffffu, (s0 == 1.f) && (s1 == 1.f))) {
#pragma unroll
            for (int nt = 0; nt < 13; nt++) {
                of[nt][0] *= s0; of[nt][1] *= s0;
                of[nt][2] *= s1; of[nt][3] *= s1;
            }
        }

        // O += P V  (V operand pairs via LDS.64)
#pragma unroll
        for (int kh = 0; kh < 2; kh++) {
            uint32_t pa[4];
            pa[0] = pp[2 * kh][0];
            pa[1] = pp[2 * kh][1];
            pa[2] = pp[2 * kh + 1][0];
            pa[3] = pp[2 * kh + 1][1];
#pragma unroll
            for (int nt = 0; nt < 13; nt++) {
                uint2 vv = *(const uint2*)&v_s[kh][tig][nt * 8 + g][0];
                MMA_BF16(of[nt], pa, vv.x, vv.y);
            }
        }
        __syncthreads();
    }

    size_t pb0 = (size_t)(z * NCH + c) * SQ + r0;
    size_t pb1 = (size_t)(z * NCH + c) * SQ + r1;
#pragma unroll
    for (int nt = 0; nt < 13; nt++) {
        int d = nt * 8 + 2 * tig;
        if (d < HDIM) {
            *(float2*)&part_o[pb0 * HDIM + d] = make_float2(of[nt][0], of[nt][1]);
            *(float2*)&part_o[pb1 * HDIM + d] = make_float2(of[nt][2], of[nt][3]);
        }
    }
    if (tig == 0) {
        part_ml[pb0 * 2] = m0; part_ml[pb0 * 2 + 1] = l0;
        part_ml[pb1 * 2] = m1; part_ml[pb1 * 2 + 1] = l1;
    }
}

__global__ void attn_combine(const float* __restrict__ part_o,
                             const float* __restrict__ part_ml,
                             uint32_t* __restrict__ ob) {
    int qi = blockIdx.x, e = blockIdx.y;
    int t = threadIdx.x, h = threadIdx.y;
    int z = e * 3 + h;
    int nch = qi / JCH + 1;
    float M = -INFINITY;
    for (int cc = 0; cc < nch; cc++)
        M = fmaxf(M, part_ml[((size_t)(z * NCH + cc) * SQ + qi) * 2]);
    float L = 0.f, a0 = 0.f, a1 = 0.f;
    for (int cc = 0; cc < nch; cc++) {
        size_t pb = (size_t)(z * NCH + cc) * SQ + qi;
        float w = __expf(part_ml[pb * 2] - M);
        L += part_ml[pb * 2 + 1] * w;
        if (t < 50) {
            float2 v = *(const float2*)&part_o[pb * HDIM + 2 * t];
            a0 += w * v.x; a1 += w * v.y;
        }
    }
    if (t < 50) {
        float inv = 1.f / L;
        ob[((size_t)e * SQ + qi) * 150 + h * 50 + t] = packbf(a0 * inv, a1 * inv);
    }
}

// ---------------- fused residual + LayerNorm ----------------
__global__ void ln_kernel(float* __restrict__ x, const float* __restrict__ delta,
                          const float* __restrict__ g, const float* __restrict__ b,
                          uint32_t* __restrict__ xb) {
    __shared__ float rs[8];
    int z = blockIdx.z;
    x += (size_t)z * SQ * EMB; delta += (size_t)z * SQ * EMB;
    g += z * EMB; b += z * EMB; xb += (size_t)z * SQ * 150;
    int r = blockIdx.x, t = threadIdx.x;
    int lane = t & 31, wid = t >> 5;
    float v[2][2];
    float s1 = 0.f, s2 = 0.f;
    {
        float2 a = *(const float2*)&x[(size_t)r * EMB + 2 * t];
        float2 d = *(const float2*)&delta[(size_t)r * EMB + 2 * t];
        v[0][0] = a.x + d.x; v[0][1] = a.y + d.y;
        s1 += v[0][0] + v[0][1];
        s2 += v[0][0] * v[0][0] + v[0][1] * v[0][1];
    }
    if (t < 22) {
        int p = t + 128;
        float2 a = *(const float2*)&x[(size_t)r * EMB + 2 * p];
        float2 d = *(const float2*)&delta[(size_t)r * EMB + 2 * p];
        v[1][0] = a.x + d.x; v[1][1] = a.y + d.y;
        s1 += v[1][0] + v[1][1];
        s2 += v[1][0] * v[1][0] + v[1][1] * v[1][1];
    }
#pragma unroll
    for (int off = 16; off > 0; off >>= 1) {
        s1 += __shfl_xor_sync(0xffffffffu, s1, off);
        s2 += __shfl_xor_sync(0xffffffffu, s2, off);
    }
    if (lane == 0) { rs[wid * 2] = s1; rs[wid * 2 + 1] = s2; }
    __syncthreads();
    float S1 = rs[0] + rs[2] + rs[4] + rs[6];
    float S2 = rs[1] + rs[3] + rs[5] + rs[7];
    float mu = S1 / (float)EMB;
    float var = S2 / (float)EMB - mu * mu;
    float rstd = rsqrtf(var + 1e-5f);
    {
        int c = 2 * t;
        float n0 = (v[0][0] - mu) * rstd * g[c] + b[c];
        float n1 = (v[0][1] - mu) * rstd * g[c + 1] + b[c + 1];
        *(float2*)&x[(size_t)r * EMB + c] = make_float2(n0, n1);
        xb[(size_t)r * 150 + t] = packbf(n0, n1);
    }
    if (t < 22) {
        int c = 2 * (t + 128);
        float n0 = (v[1][0] - mu) * rstd * g[c] + b[c];
        float n1 = (v[1][1] - mu) * rstd * g[c + 1] + b[c + 1];
        *(float2*)&x[(size_t)r * EMB + c] = make_float2(n0, n1);
        xb[(size_t)r * 150 + t + 128] = packbf(n0, n1);
    }
}

// ---------------- row softmax over A: fp32 in, bf16 out ----------------
__global__ void softmax_rows(const float* __restrict__ A, __nv_bfloat16* __restrict__ Ab) {
    __shared__ float row[SQ];
    __shared__ float red[256];
    int r = blockIdx.x, t = threadIdx.x;
    float mx = -INFINITY;
    for (int j = t; j < SQ; j += 256) { float v = A[(size_t)r * SQ + j]; row[j] = v; mx = fmaxf(mx, v); }
    red[t] = mx; __syncthreads();
    for (int off = 128; off > 0; off >>= 1) { if (t < off) red[t] = fmaxf(red[t], red[t + off]); __syncthreads(); }
    mx = red[0];
    __syncthreads();
    float s = 0.f;
    for (int j = t; j < SQ; j += 256) { float e = __expf(row[j] - mx); row[j] = e; s += e; }
    red[t] = s; __syncthreads();
    for (int off = 128; off > 0; off >>= 1) { if (t < off) red[t] += red[t + off]; __syncthreads(); }
    float inv = 1.f / red[0];
    uint32_t* out = (uint32_t*)(Ab + (size_t)r * SQ);
    for (int j = 2 * t; j < SQ; j += 512)
        out[j >> 1] = packbf(row[j] * inv, row[j + 1] * inv);
}

// ---------------- coalesced colsum of elementwise max ----------------
__global__ void colsum_partial(const float* __restrict__ H, const float* __restrict__ P,
                               const float* __restrict__ G, const float* __restrict__ Q,
                               float* __restrict__ part) {
    int chunk = blockIdx.x, pair = blockIdx.y;
    int c = threadIdx.x;
    const float* X = pair ? G : H;
    const float* Y = pair ? Q : P;
    int r0 = chunk * 128;
    float s = 0.f;
    for (int r = r0; r < r0 + 128; r++)
        s += fmaxf(X[(size_t)r * EMB + c], Y[(size_t)r * EMB + c]);
    part[((size_t)pair * 32 + chunk) * EMB + c] = s;
}
__global__ void colsum_final(const float* __restrict__ part, float* __restrict__ suv) {
    int j = threadIdx.x;
    int pair = j / EMB, c = j - pair * EMB;
    float s = 0.f;
#pragma unroll
    for (int ch = 0; ch < 32; ch++)
        s += part[((size_t)pair * 32 + ch) * EMB + c];
    suv[j] = s;
}

// ---------------- tiny FC layers ----------------
__global__ void fc1_kernel(const float* __restrict__ inp, const float* __restrict__ w,
                           const float* __restrict__ b, float* __restrict__ out) {
    __shared__ float red[128];
    int i = blockIdx.x, t = threadIdx.x;
    float s = 0.f;
    for (int j = t; j < 2 * EMB; j += 128) s += inp[j] * w[(size_t)i * 2 * EMB + j];
    red[t] = s; __syncthreads();
    for (int off = 64; off > 0; off >>= 1) { if (t < off) red[t] += red[t + off]; __syncthreads(); }
    if (t == 0) out[i] = fmaxf(red[0] + b[i], 0.f);
}

__global__ void fc2_kernel(const float* __restrict__ inp, const float* __restrict__ w,
                           const float* __restrict__ b, float* __restrict__ out) {
    __shared__ float red[256];
    int t = threadIdx.x;
    float s = 0.f;
    for (int j = t; j < EMB; j += 256) s += inp[j] * w[j];
    red[t] = s; __syncthreads();
    for (int off = 128; off > 0; off >>= 1) { if (t < off) red[t] += red[t + off]; __syncthreads(); }
    if (t == 0) out[0] = red[0] + b[0];
}

// ---------------- host orchestration ----------------
extern "C" void kernel_launch(void* const* d_in, const int* in_sizes, int n_in,
                              void* d_out, int out_size) {
    const float* solv = (const float*)d_in[0];
    const float* solu = (const float*)d_in[1];
    const float* ipw  = (const float*)d_in[2];
    const float* ipb  = (const float*)d_in[3];
    const float* ow   = (const float*)d_in[4];
    const float* ob_b = (const float*)d_in[5];
    const float* g1   = (const float*)d_in[6];
    const float* b1   = (const float*)d_in[7];
    const float* w1   = (const float*)d_in[8];
    const float* bb1  = (const float*)d_in[9];
    const float* w2   = (const float*)d_in[10];
    const float* bb2  = (const float*)d_in[11];
    const float* g2   = (const float*)d_in[12];
    const float* b2   = (const float*)d_in[13];
    const float* fc1w = (const float*)d_in[14];
    const float* fc1b = (const float*)d_in[15];
    const float* fc2w = (const float*)d_in[16];
    const float* fc2b = (const float*)d_in[17];

    float *x, *t1, *A, *P, *Q, *Pp, *Qp, *po, *pml, *cpart, *suv, *fc1o;
    uint32_t *xb, *xbT, *wp, *qkvb, *ob, *ffb;
    __nv_bfloat16* Ab;
    cudaGetSymbolAddress((void**)&x,    g_x);
    cudaGetSymbolAddress((void**)&xb,   g_xb);
    cudaGetSymbolAddress((void**)&xbT,  g_xbT);
    cudaGetSymbolAddress((void**)&wp,   g_wpack);
    cudaGetSymbolAddress((void**)&qkvb, g_qkvb);
    cudaGetSymbolAddress((void**)&ob,   g_ob);
    cudaGetSymbolAddress((void**)&t1,   g_t1);
    cudaGetSymbolAddress((void**)&ffb,  g_ffb);
    cudaGetSymbolAddress((void**)&A,    g_A);
    cudaGetSymbolAddress((void**)&Ab,   g_Ab);
    cudaGetSymbolAddress((void**)&P,    g_P);
    cudaGetSymbolAddress((void**)&Q,    g_Q);
    cudaGetSymbolAddress((void**)&Pp,   g_Pp);
    cudaGetSymbolAddress((void**)&Qp,   g_Qp);
    cudaGetSymbolAddress((void**)&po,   g_part_o);
    cudaGetSymbolAddress((void**)&pml,  g_part_ml);
    cudaGetSymbolAddress((void**)&cpart, g_colpart);
    cudaGetSymbolAddress((void**)&suv,  g_suv);
    cudaGetSymbolAddress((void**)&fc1o, g_fc1o);

    const size_t SE = (size_t)SQ * EMB;
    uint32_t* ipwb = wp;
    uint32_t* owb  = wp + 270000;
    uint32_t* w1b  = wp + 360000;
    uint32_t* w2b  = wp + 420000;

    pack4<<<(480000 + 255) / 256, 256>>>(ipw, ow, w1, w2, wp);

    add_pe_kernel<<<dim3((SQ * 150 + 255) / 256, 1, 2), 256>>>(solv, solu, x, xb);

    mma2<0, 0, 0, 2><<<dim3(15, 32, 2), 256>>>(
        (const __nv_bfloat16*)xb, (const __nv_bfloat16*)ipwb, ipb, (float*)qkvb,
        SQ, 3 * EMB, EMB, EMB, EMB,
        (size_t)SQ * EMB, (size_t)3 * EMB * EMB, 3 * EMB, (size_t)SQ * QKVS, 0);

    attn_mma_kernel<<<dim3(SQ / QB, NCH, 6), 128>>>(qkvb, po, pml);
    attn_combine<<<dim3(SQ, 2), dim3(64, 3)>>>(po, pml, ob);

    mma2<0, 0, 0, 0><<<dim3(5, 32, 2), 256>>>(
        (const __nv_bfloat16*)ob, (const __nv_bfloat16*)owb, ob_b, t1,
        SQ, EMB, EMB, EMB, EMB,
        (size_t)SQ * EMB, (size_t)EMB * EMB, EMB, SE, 0);
    ln_kernel<<<dim3(SQ, 1, 2), 128>>>(x, t1, g1, b1, xb);

    mma2<0, 1, 0, 1><<<dim3(4, 32, 2), 256>>>(
        (const __nv_bfloat16*)xb, (const __nv_bfloat16*)w1b, bb1, (float*)ffb,
        SQ, NHID, EMB, EMB, EMB,
        (size_t)SQ * EMB, (size_t)NHID * EMB, NHID, (size_t)SQ * 100, 0);
    mma2<0, 0, 0, 0><<<dim3(5, 32, 2), 256>>>(
        (const __nv_bfloat16*)ffb, (const __nv_bfloat16*)w2b, bb2, t1,
        SQ, EMB, NHID, NHID, NHID,
        (size_t)SQ * NHID, (size_t)EMB * NHID, EMB, SE, 0);
    ln_kernel<<<dim3(SQ, 1, 2), 128>>>(x, t1, g2, b2, xb);

    float* H = x;
    float* G = x + SE;
    uint32_t* Hb = xb;
    uint32_t* Gb = xb + (size_t)SQ * 150;

    transpose_pack<<<dim3(SQ / 64, 5, 2), 256>>>(x, xbT);
    const __nv_bfloat16* HbT = (const __nv_bfloat16*)xbT;
    const __nv_bfloat16* GbT = (const __nv_bfloat16*)xbT + (size_t)EMB * SQ;

    mma2<0, 0, 0, 0><<<dim3(64, 32, 1), 256>>>(
        (const __nv_bfloat16*)Hb, (const __nv_bfloat16*)Gb, (const float*)nullptr, A,
        SQ, SQ, EMB, EMB, EMB, 0, 0, 0, 0, 0);
    softmax_rows<<<SQ, 256>>>(A, Ab);

    mma2_pq<<<dim3(5, 32, 2 * NCH), 256>>>(Ab, GbT, HbT, Pp, Qp);
    reduce_pq<<<dim3((SQ * EMB / 4 + 255) / 256, 2), 256>>>(Pp, Qp, P, Q);

    colsum_partial<<<dim3(32, 2), 300>>>(H, P, G, Q, cpart);
    colsum_final<<<1, 600>>>(cpart, suv);

    fc1_kernel<<<EMB, 128>>>(suv, fc1w, fc1b, fc1o);
    fc2_kernel<<<1, 256>>>(fc1o, fc2w, fc2b, (float*)d_out);
}

// round 15
// speedup vs baseline: 1.0469x; 1.0469x over previous
#include <cuda_runtime.h>
#include <cuda_bf16.h>
#include <math.h>
#include <stdint.h>

#define SQ   4096
#define EMB  300
#define NH   3
#define HDIM 100
#define NHID 200
#define QB   64
#define TJ   32
#define JCH  1024
#define NCH  4
#define KSPL 1024
#define ASTR 136
#define BSTR 72
#define QKVS 468   // padded qkv row stride (words): 3 segs x 156, head stride 52

// ---------------- scratch ----------------
__device__ float g_x[2 * SQ * EMB];
__device__ uint32_t g_xb[2 * SQ * 150];
__device__ uint32_t g_xbT[2 * EMB * (SQ / 2)];
__device__ uint32_t g_wpack[480000];
__device__ __align__(16) uint32_t g_qkvb[2 * SQ * QKVS];
__device__ uint32_t g_ob[2 * SQ * 150];
__device__ float g_t1[2 * SQ * EMB];
__device__ uint32_t g_ffb[2 * SQ * 100];
__device__ float g_A[SQ * SQ];
__device__ __nv_bfloat16 g_Ab[SQ * SQ];
__device__ float g_P[SQ * EMB];
__device__ float g_Q[SQ * EMB];
__device__ float g_Pp[NCH * SQ * EMB];
__device__ float g_Qp[NCH * SQ * EMB];
__device__ float g_part_o[6 * NCH * SQ * HDIM];
__device__ float g_part_ml[6 * NCH * SQ * 2];
__device__ float g_colpart[2 * 32 * EMB];
__device__ float g_suv[2 * EMB];
__device__ float g_fc1o[EMB];

// ---------------- bf16 helpers ----------------
__device__ __forceinline__ uint32_t packbf(float lo, float hi) {
    uint32_t r;
    asm("cvt.rn.bf16x2.f32 %0, %1, %2;" : "=r"(r) : "f"(hi), "f"(lo));
    return r;
}

#define MMA_BF16(C, A, B0, B1)                                                  \
    asm volatile(                                                               \
        "mma.sync.aligned.m16n8k16.row.col.f32.bf16.bf16.f32 "                  \
        "{%0,%1,%2,%3},{%4,%5,%6,%7},{%8,%9},{%0,%1,%2,%3};"                    \
        : "+f"((C)[0]), "+f"((C)[1]), "+f"((C)[2]), "+f"((C)[3])                \
        : "r"((A)[0]), "r"((A)[1]), "r"((A)[2]), "r"((A)[3]), "r"(B0), "r"(B1))

#define LDMX4(R, ADDR)                                                          \
    asm volatile("ldmatrix.sync.aligned.m8n8.x4.shared.b16 {%0,%1,%2,%3}, [%4];" \
        : "=r"((R)[0]), "=r"((R)[1]), "=r"((R)[2]), "=r"((R)[3]) : "r"(ADDR))

// ---------------- packing kernels ----------------
__global__ void pack4(const float* __restrict__ ipw, const float* __restrict__ ow,
                      const float* __restrict__ w1, const float* __restrict__ w2,
                      uint32_t* __restrict__ dst) {
    int i = blockIdx.x * 256 + threadIdx.x;
    if (i >= 480000) return;
    const float* src;
    int off;
    if (i < 270000)      { src = ipw; off = i; }
    else if (i < 360000) { src = ow;  off = i - 270000; }
    else if (i < 420000) { src = w1;  off = i - 360000; }
    else                 { src = w2;  off = i - 420000; }
    float2 v = ((const float2*)src)[off];
    dst[i] = packbf(v.x, v.y);
}

__global__ void transpose_pack(const float* __restrict__ x, uint32_t* __restrict__ xT) {
    __shared__ float tile[64][65];
    int z = blockIdx.z;
    int s0 = blockIdx.x * 64, c0 = blockIdx.y * 64;
    int t = threadIdx.x;
#pragma unroll
    for (int i = 0; i < 16; i++) {
        int idx = t + i * 256;
        int ls = idx >> 6, lc = idx & 63;
        int c = c0 + lc;
        tile[ls][lc] = (c < EMB) ? x[(size_t)z * SQ * EMB + (size_t)(s0 + ls) * EMB + c] : 0.f;
    }
    __syncthreads();
#pragma unroll
    for (int i = 0; i < 8; i++) {
        int idx = t + i * 256;
        int lc = idx >> 5, lsp = idx & 31;
        int c = c0 + lc;
        if (c < EMB)
            xT[(size_t)z * EMB * (SQ / 2) + (size_t)c * (SQ / 2) + (s0 >> 1) + lsp] =
                packbf(tile[2 * lsp][lc], tile[2 * lsp + 1][lc]);
    }
}

// ---------------- positional encoding + add ----------------
__global__ void add_pe_kernel(const float* __restrict__ solv, const float* __restrict__ solu,
                              float* __restrict__ x, uint32_t* __restrict__ xb) {
    int p = blockIdx.x * blockDim.x + threadIdx.x;
    if (p >= SQ * 150) return;
    int z = blockIdx.z;
    const float* src = z ? solu : solv;
    int s = p / 150, pc = p - s * 150, c = 2 * pc;
    float dv = __expf(-(float)c * (logf(10000.0f) / (float)EMB));
    float arg = (float)s * dv;
    float pe0 = sinf(arg), pe1 = cosf(arg);
    float2 a = *(const float2*)&src[(size_t)s * EMB + c];
    float v0 = a.x + pe0, v1 = a.y + pe1;
    *(float2*)&x[(size_t)z * SQ * EMB + (size_t)s * EMB + c] = make_float2(v0, v1);
    xb[(size_t)z * SQ * 150 + p] = packbf(v0, v1);
}

// ---------------- all-bf16 tensor-core GEMM ----------------
template<int TA, int RELU, int SPLITK, int BF16OUT>
__global__ __launch_bounds__(256, 2)
void mma2(const __nv_bfloat16* __restrict__ A, const __nv_bfloat16* __restrict__ B,
          const float* __restrict__ bias, float* __restrict__ C,
          int M, int N, int K, int lda, int ldb,
          size_t sA, size_t sB, size_t sBias, size_t sC, int kc) {
    int z = blockIdx.z;
    int k_begin = 0, k_end = K;
    if (SPLITK) {
        k_begin = z * kc;
        k_end = min(K, k_begin + kc);
        C += (size_t)z * sC;
    } else {
        A += (size_t)z * sA; B += (size_t)z * sB; C += (size_t)z * sC;
        if (bias) bias += (size_t)z * sBias;
    }
    uint32_t* C32 = (uint32_t*)C;

    __shared__ uint32_t As[2][16][ASTR];
    __shared__ uint32_t Bs[2][16][BSTR];

    int t = threadIdx.x;
    int warp = t >> 5, lane = t & 31;
    int g = lane >> 2, tig = lane & 3;
    int wm = warp & 3, wn = warp >> 2;
    int row0 = blockIdx.y * 128, col0 = blockIdx.x * 64;
    int wr0 = wm * 32, wc0 = wn * 32;

    float acc[2][4][4];
#pragma unroll
    for (int i = 0; i < 2; i++)
#pragma unroll
        for (int j = 0; j < 4; j++)
#pragma unroll
            for (int h = 0; h < 4; h++) acc[i][j][h] = 0.f;

    uint32_t ra[8], rb[4];

    auto loadA = [&](int kt) {
        if (!TA) {
            int m = t >> 1, kq = (t & 1) * 16;
            const uint32_t* Ap = (const uint32_t*)(A + (size_t)(row0 + m) * lda + kt + kq);
            if (kt + kq + 15 < k_end) {
#pragma unroll
                for (int u = 0; u < 8; u++) ra[u] = Ap[u];
            } else {
                const unsigned short* A16 = (const unsigned short*)(A + (size_t)(row0 + m) * lda);
#pragma unroll
                for (int u = 0; u < 8; u++) {
                    int gk = kt + kq + 2 * u;
                    uint32_t lo = (gk < k_end) ? A16[gk] : 0;
                    uint32_t hi = (gk + 1 < k_end) ? A16[gk + 1] : 0;
                    ra[u] = lo | (hi << 16);
                }
            }
        } else {
            int kp = t >> 4, mq = (t & 15) * 8;
            int gk0 = kt + 2 * kp;
            bool ok0 = gk0 < k_end, ok1 = gk0 + 1 < k_end;
            const uint32_t* r0p = (const uint32_t*)(A + (size_t)gk0 * lda + row0 + mq);
            const uint32_t* r1p = (const uint32_t*)(A + (size_t)(gk0 + 1) * lda + row0 + mq);
            if (ok1) {
#pragma unroll
                for (int u = 0; u < 4; u++) {
                    uint32_t w0 = r0p[u], w1 = r1p[u];
                    ra[2 * u]     = __byte_perm(w0, w1, 0x5410);
                    ra[2 * u + 1] = __byte_perm(w0, w1, 0x7632);
                }
            } else {
#pragma unroll
                for (int u = 0; u < 4; u++) {
                    uint32_t w0 = ok0 ? r0p[u] : 0;
                    ra[2 * u]     = __byte_perm(w0, 0u, 0x5410);
                    ra[2 * u + 1] = __byte_perm(w0, 0u, 0x7632);
                }
            }
        }
    };
    auto loadB = [&](int kt) {
        int n = t >> 2, kq = (t & 3) * 8;
        int gn = col0 + n;
        bool okn = gn < N;
        const uint32_t* Bp = (const uint32_t*)(B + (size_t)gn * ldb + kt + kq);
        if (okn && kt + kq + 7 < k_end) {
#pragma unroll
            for (int u = 0; u < 4; u++) rb[u] = Bp[u];
        } else {
            const unsigned short* B16 = (const unsigned short*)(B + (size_t)gn * ldb);
#pragma unroll
            for (int u = 0; u < 4; u++) {
                int gk = kt + kq + 2 * u;
                uint32_t lo = (okn && gk < k_end) ? B16[gk] : 0;
                uint32_t hi = (okn && gk + 1 < k_end) ? B16[gk + 1] : 0;
                rb[u] = lo | (hi << 16);
            }
        }
    };
    auto storeA = [&](int bf) {
        if (!TA) {
            int m = t >> 1, kp0 = (t & 1) * 8;
#pragma unroll
            for (int u = 0; u < 8; u++) As[bf][kp0 + u][m] = ra[u];
        } else {
            int kp = t >> 4, mq = (t & 15) * 8;
#pragma unroll
            for (int u = 0; u < 8; u++) As[bf][kp][mq + u] = ra[u];
        }
    };
    auto storeB = [&](int bf) {
        int n = t >> 2, kp0 = (t & 3) * 4;
#pragma unroll
        for (int u = 0; u < 4; u++) Bs[bf][kp0 + u][n] = rb[u];
    };

    int nk = (k_end - k_begin + 31) >> 5;
    loadA(k_begin); loadB(k_begin);
    storeA(0); storeB(0);
    __syncthreads();

    int buf = 0;
    for (int it = 0; it < nk; it++) {
        if (it + 1 < nk) { loadA(k_begin + (it + 1) * 32); loadB(k_begin + (it + 1) * 32); }
#pragma unroll
        for (int ks = 0; ks < 16; ks += 8) {
            uint32_t a[2][4], b[4][2];
#pragma unroll
            for (int i = 0; i < 2; i++) {
                int mb = wr0 + i * 16;
                a[i][0] = As[buf][ks + tig][mb + g];
                a[i][1] = As[buf][ks + tig][mb + 8 + g];
                a[i][2] = As[buf][ks + tig + 4][mb + g];
                a[i][3] = As[buf][ks + tig + 4][mb + 8 + g];
            }
#pragma unroll
            for (int j = 0; j < 4; j++) {
                int nb = wc0 + j * 8;
                b[j][0] = Bs[buf][ks + tig][nb + g];
                b[j][1] = Bs[buf][ks + tig + 4][nb + g];
            }
#pragma unroll
            for (int i = 0; i < 2; i++)
#pragma unroll
                for (int j = 0; j < 4; j++)
                    MMA_BF16(acc[i][j], a[i], b[j][0], b[j][1]);
        }
        if (it + 1 < nk) {
            storeA(1 - buf); storeB(1 - buf);
            __syncthreads();
            buf ^= 1;
        }
    }

#pragma unroll
    for (int i = 0; i < 2; i++) {
        int r0 = row0 + wr0 + i * 16 + g;
#pragma unroll
        for (int j = 0; j < 4; j++) {
            int cc = col0 + wc0 + j * 8 + tig * 2;
#pragma unroll
            for (int h = 0; h < 2; h++) {
                int gr = r0 + h * 8;
                float v0 = acc[i][j][h * 2], v1 = acc[i][j][h * 2 + 1];
                if (!SPLITK && bias) {
                    if (cc < N) v0 += bias[cc];
                    if (cc + 1 < N) v1 += bias[cc + 1];
                }
                if (RELU) { v0 = fmaxf(v0, 0.f); v1 = fmaxf(v1, 0.f); }
                if (BF16OUT == 2) {
                    if (cc < N) {
                        int seg = cc / 300, rem = cc - seg * 300;
                        int hh = rem / 100, wi = rem - hh * 100;
                        C32[(size_t)gr * QKVS + seg * 156 + hh * 52 + (wi >> 1)] = packbf(v0, v1);
                    }
                } else if (BF16OUT == 1) {
                    if (cc < N)
                        C32[(size_t)gr * (N >> 1) + (cc >> 1)] = packbf(v0, v1);
                } else if (cc + 1 < N) {
                    *(float2*)&C[(size_t)gr * N + cc] = make_float2(v0, v1);
                } else if (cc < N) {
                    C[(size_t)gr * N + cc] = v0;
                }
            }
        }
    }
}

// ---------------- fused P+Q split-K GEMM ----------------
__global__ __launch_bounds__(256, 2)
void mma2_pq(const __nv_bfloat16* __restrict__ Ain, const __nv_bfloat16* __restrict__ BP,
             const __nv_bfloat16* __restrict__ BQ, float* __restrict__ CP,
             float* __restrict__ CQ) {
    int z = blockIdx.z;
    int ta = (z >= NCH) ? 1 : 0;
    int zz = ta ? z - NCH : z;
    int k_begin = zz * KSPL;
    const __nv_bfloat16* B = ta ? BQ : BP;
    float* C = (ta ? CQ : CP) + (size_t)zz * SQ * EMB;
    const int lda = SQ, ldb = SQ, N = EMB;

    __shared__ uint32_t As[2][16][ASTR];
    __shared__ uint32_t Bs[2][16][BSTR];

    int t = threadIdx.x;
    int warp = t >> 5, lane = t & 31;
    int g = lane >> 2, tig = lane & 3;
    int wm = warp & 3, wn = warp >> 2;
    int row0 = blockIdx.y * 128, col0 = blockIdx.x * 64;
    int wr0 = wm * 32, wc0 = wn * 32;

    float acc[2][4][4];
#pragma unroll
    for (int i = 0; i < 2; i++)
#pragma unroll
        for (int j = 0; j < 4; j++)
#pragma unroll
            for (int h = 0; h < 4; h++) acc[i][j][h] = 0.f;

    uint32_t ra[8], rb[4];

    auto loadA = [&](int kt) {
        if (!ta) {
            int m = t >> 1, kq = (t & 1) * 16;
            const uint32_t* Ap = (const uint32_t*)(Ain + (size_t)(row0 + m) * lda + kt + kq);
#pragma unroll
            for (int u = 0; u < 8; u++) ra[u] = Ap[u];
        } else {
            int kp = t >> 4, mq = (t & 15) * 8;
            int gk0 = kt + 2 * kp;
            const uint32_t* r0p = (const uint32_t*)(Ain + (size_t)gk0 * lda + row0 + mq);
            const uint32_t* r1p = (const uint32_t*)(Ain + (size_t)(gk0 + 1) * lda + row0 + mq);
#pragma unroll
            for (int u = 0; u < 4; u++) {
                uint32_t w0 = r0p[u], w1 = r1p[u];
                ra[2 * u]     = __byte_perm(w0, w1, 0x5410);
                ra[2 * u + 1] = __byte_perm(w0, w1, 0x7632);
            }
        }
    };
    auto loadB = [&](int kt) {
        int n = t >> 2, kq = (t & 3) * 8;
        int gn = col0 + n;
        if (gn < N) {
            const uint32_t* Bp = (const uint32_t*)(B + (size_t)gn * ldb + kt + kq);
#pragma unroll
            for (int u = 0; u < 4; u++) rb[u] = Bp[u];
        } else {
#pragma unroll
            for (int u = 0; u < 4; u++) rb[u] = 0u;
        }
    };
    auto storeA = [&](int bf) {
        if (!ta) {
            int m = t >> 1, kp0 = (t & 1) * 8;
#pragma unroll
            for (int u = 0; u < 8; u++) As[bf][kp0 + u][m] = ra[u];
        } else {
            int kp = t >> 4, mq = (t & 15) * 8;
#pragma unroll
            for (int u = 0; u < 8; u++) As[bf][kp][mq + u] = ra[u];
        }
    };
    auto storeB = [&](int bf) {
        int n = t >> 2, kp0 = (t & 3) * 4;
#pragma unroll
        for (int u = 0; u < 4; u++) Bs[bf][kp0 + u][n] = rb[u];
    };

    const int nk = KSPL >> 5;
    loadA(k_begin); loadB(k_begin);
    storeA(0); storeB(0);
    __syncthreads();

    int buf = 0;
    for (int it = 0; it < nk; it++) {
        if (it + 1 < nk) { loadA(k_begin + (it + 1) * 32); loadB(k_begin + (it + 1) * 32); }
#pragma unroll
        for (int ks = 0; ks < 16; ks += 8) {
            uint32_t a[2][4], b[4][2];
#pragma unroll
            for (int i = 0; i < 2; i++) {
                int mb = wr0 + i * 16;
                a[i][0] = As[buf][ks + tig][mb + g];
                a[i][1] = As[buf][ks + tig][mb + 8 + g];
                a[i][2] = As[buf][ks + tig + 4][mb + g];
                a[i][3] = As[buf][ks + tig + 4][mb + 8 + g];
            }
#pragma unroll
            for (int j = 0; j < 4; j++) {
                int nb = wc0 + j * 8;
                b[j][0] = Bs[buf][ks + tig][nb + g];
                b[j][1] = Bs[buf][ks + tig + 4][nb + g];
            }
#pragma unroll
            for (int i = 0; i < 2; i++)
#pragma unroll
                for (int j = 0; j < 4; j++)
                    MMA_BF16(acc[i][j], a[i], b[j][0], b[j][1]);
        }
        if (it + 1 < nk) {
            storeA(1 - buf); storeB(1 - buf);
            __syncthreads();
            buf ^= 1;
        }
    }

#pragma unroll
    for (int i = 0; i < 2; i++) {
        int r0 = row0 + wr0 + i * 16 + g;
#pragma unroll
        for (int j = 0; j < 4; j++) {
            int cc = col0 + wc0 + j * 8 + tig * 2;
#pragma unroll
            for (int h = 0; h < 2; h++) {
                int gr = r0 + h * 8;
                float v0 = acc[i][j][h * 2], v1 = acc[i][j][h * 2 + 1];
                if (cc + 1 < N) {
                    *(float2*)&C[(size_t)gr * N + cc] = make_float2(v0, v1);
                } else if (cc < N) {
                    C[(size_t)gr * N + cc] = v0;
                }
            }
        }
    }
}

// ---------------- split-K reduce ----------------
__global__ void reduce_pq(const float* __restrict__ Pp, const float* __restrict__ Qp,
                          float* __restrict__ P, float* __restrict__ Q) {
    int idx = blockIdx.x * 256 + threadIdx.x;
    if (idx >= SQ * EMB / 4) return;
    const float* src = blockIdx.y ? Qp : Pp;
    float* dst = blockIdx.y ? Q : P;
    float4 r = make_float4(0.f, 0.f, 0.f, 0.f);
#pragma unroll
    for (int c = 0; c < NCH; c++) {
        float4 a = ((const float4*)(src + (size_t)c * SQ * EMB))[idx];
        r.x += a.x; r.y += a.y; r.z += a.z; r.w += a.w;
    }
    ((float4*)dst)[idx] = r;
}

// ---------------- bf16 flash attention (R13 layout + rescale skip) ----------------
__global__ __launch_bounds__(128, 5)
void attn_mma_kernel(const uint32_t* __restrict__ qb_all,
                     float* __restrict__ part_o, float* __restrict__ part_ml) {
    __shared__ __align__(16) uint32_t k_s[TJ][60];
    __shared__ __align__(16) uint32_t v_s[16][108];
    __shared__ __align__(16) uint32_t q_s[4][16][60];

    int z = blockIdx.z, e = z / 3, h = z % 3;
    int qt = (int)gridDim.x - 1 - (int)blockIdx.x;
    int q0 = qt * QB;
    int c = blockIdx.y, c0 = c * JCH;
    if (c0 > q0 + QB - 1) return;

    const uint32_t* qb = qb_all + (size_t)e * SQ * QKVS;
    int t = threadIdx.x, w = t >> 5, lane = t & 31;
    int g = lane >> 2, tig = lane & 3;

    int r0 = q0 + w * 16 + g;
    int r1 = r0 + 8;

    // stage Q fragments into smem once
    {
        const uint32_t* q0p = qb + (size_t)r0 * QKVS + h * 52;
        const uint32_t* q1p = qb + (size_t)r1 * QKVS + h * 52;
#pragma unroll
        for (int s = 0; s < 7; s++) {
            int dp0 = s * 8 + tig, dp1 = dp0 + 4;
            q_s[w][g][dp0]     = dp0 < 50 ? q0p[dp0] : 0u;
            q_s[w][g + 8][dp0] = dp0 < 50 ? q1p[dp0] : 0u;
            q_s[w][g][dp1]     = dp1 < 50 ? q0p[dp1] : 0u;
            q_s[w][g + 8][dp1] = dp1 < 50 ? q1p[dp1] : 0u;
        }
    }
    // zero pad columns once
    for (int idx = t; idx < 32 * 6; idx += 128) k_s[idx / 6][50 + idx % 6] = 0u;
    for (int idx = t; idx < 16 * 8; idx += 128) v_s[idx / 8][100 + idx % 8] = 0u;

    uint32_t kbase0, kbase1, qbase;
    {
        int tile = lane >> 3, row = lane & 7;
        int krow = (tile >> 1) * 8 + row;
        int kword = (tile & 1) * 4;
        kbase0 = (uint32_t)__cvta_generic_to_shared(&k_s[krow][kword]);
        kbase1 = (uint32_t)__cvta_generic_to_shared(&k_s[16 + krow][kword]);
        int qrow = ((tile & 1) ? 8 : 0) + row;
        int qword = (tile >> 1) * 4;
        qbase = (uint32_t)__cvta_generic_to_shared(&q_s[w][qrow][qword]);
    }

    float of[13][4];
#pragma unroll
    for (int nt = 0; nt < 13; nt++) { of[nt][0] = of[nt][1] = of[nt][2] = of[nt][3] = 0.f; }
    float m0 = -INFINITY, m1 = -INFINITY, l0 = 0.f, l1 = 0.f;

    int jend = min(c0 + JCH, q0 + QB);
    for (int jt = c0; jt < jend; jt += TJ) {
        // K stage: vectorized
        for (int idx = t; idx < 32 * 13; idx += 128) {
            int row = idx / 13, sl = idx - row * 13;
            const uint32_t* src = qb + (size_t)(jt + row) * QKVS + 156 + h * 52;
            if (sl < 12) {
                *(uint4*)&k_s[row][4 * sl] = *(const uint4*)(src + 4 * sl);
            } else {
                *(uint2*)&k_s[row][48] = *(const uint2*)(src + 48);
            }
        }
        // V stage: interleave two j rows, vectorized (R13 layout)
        for (int idx = t; idx < 16 * 13; idx += 128) {
            int jp = idx / 13, sl = idx - jp * 13;
            const uint32_t* s0p = qb + (size_t)(jt + 2 * jp) * QKVS + 312 + h * 52;
            const uint32_t* s1p = s0p + QKVS;
            if (sl < 12) {
                uint4 a = *(const uint4*)(s0p + 4 * sl);
                uint4 b = *(const uint4*)(s1p + 4 * sl);
                uint4 o0, o1;
                o0.x = __byte_perm(a.x, b.x, 0x5410); o0.y = __byte_perm(a.x, b.x, 0x7632);
                o0.z = __byte_perm(a.y, b.y, 0x5410); o0.w = __byte_perm(a.y, b.y, 0x7632);
                o1.x = __byte_perm(a.z, b.z, 0x5410); o1.y = __byte_perm(a.z, b.z, 0x7632);
                o1.z = __byte_perm(a.w, b.w, 0x5410); o1.w = __byte_perm(a.w, b.w, 0x7632);
                *(uint4*)&v_s[jp][8 * sl] = o0;
                *(uint4*)&v_s[jp][8 * sl + 4] = o1;
            } else {
                uint2 a = *(const uint2*)(s0p + 48);
                uint2 b = *(const uint2*)(s1p + 48);
                uint4 o;
                o.x = __byte_perm(a.x, b.x, 0x5410); o.y = __byte_perm(a.x, b.x, 0x7632);
                o.z = __byte_perm(a.y, b.y, 0x5410); o.w = __byte_perm(a.y, b.y, 0x7632);
                *(uint4*)&v_s[jp][96] = o;
            }
        }
        __syncthreads();

        // S = Q K^T via ldmatrix fragments
        float sc[4][4];
#pragma unroll
        for (int nt = 0; nt < 4; nt++) { sc[nt][0] = sc[nt][1] = sc[nt][2] = sc[nt][3] = 0.f; }
#pragma unroll
        for (int s = 0; s < 7; s++) {
            uint32_t qa[4], kb0[4], kb1[4];
            LDMX4(qa, qbase + s * 32);
            LDMX4(kb0, kbase0 + s * 32);
            LDMX4(kb1, kbase1 + s * 32);
            MMA_BF16(sc[0], qa, kb0[0], kb0[1]);
            MMA_BF16(sc[1], qa, kb0[2], kb0[3]);
            MMA_BF16(sc[2], qa, kb1[0], kb1[1]);
            MMA_BF16(sc[3], qa, kb1[2], kb1[3]);
        }
#pragma unroll
        for (int nt = 0; nt < 4; nt++) {
            sc[nt][0] *= 0.1f; sc[nt][1] *= 0.1f; sc[nt][2] *= 0.1f; sc[nt][3] *= 0.1f;
        }

        if (jt + TJ > q0) {
#pragma unroll
            for (int nt = 0; nt < 4; nt++) {
                int jb = jt + nt * 8 + 2 * tig;
                if (jb > r0)     sc[nt][0] = -INFINITY;
                if (jb + 1 > r0) sc[nt][1] = -INFINITY;
                if (jb > r1)     sc[nt][2] = -INFINITY;
                if (jb + 1 > r1) sc[nt][3] = -INFINITY;
            }
        }

        float rm0 = -INFINITY, rm1 = -INFINITY;
#pragma unroll
        for (int nt = 0; nt < 4; nt++) {
            rm0 = fmaxf(rm0, fmaxf(sc[nt][0], sc[nt][1]));
            rm1 = fmaxf(rm1, fmaxf(sc[nt][2], sc[nt][3]));
        }
        rm0 = fmaxf(rm0, __shfl_xor_sync(0xffffffffu, rm0, 1));
        rm0 = fmaxf(rm0, __shfl_xor_sync(0xffffffffu, rm0, 2));
        rm1 = fmaxf(rm1, __shfl_xor_sync(0xffffffffu, rm1, 1));
        rm1 = fmaxf(rm1, __shfl_xor_sync(0xffffffffu, rm1, 2));
        float mn0 = fmaxf(m0, rm0), mn1 = fmaxf(m1, rm1);
        float s0 = __expf(m0 - mn0), s1 = __expf(m1 - mn1);

        uint32_t pp[4][2];
        float rs0 = 0.f, rs1 = 0.f;
#pragma unroll
        for (int nt = 0; nt < 4; nt++) {
            float p0 = __expf(sc[nt][0] - mn0);
            float p1 = __expf(sc[nt][1] - mn0);
            float p2 = __expf(sc[nt][2] - mn1);
            float p3 = __expf(sc[nt][3] - mn1);
            rs0 += p0 + p1;
            rs1 += p2 + p3;
            pp[nt][0] = packbf(p0, p1);
            pp[nt][1] = packbf(p2, p3);
        }
        rs0 += __shfl_xor_sync(0xffffffffu, rs0, 1);
        rs0 += __shfl_xor_sync(0xffffffffu, rs0, 2);
        rs1 += __shfl_xor_sync(0xffffffffu, rs1, 1);
        rs1 += __shfl_xor_sync(0xffffffffu, rs1, 2);
        l0 = l0 * s0 + rs0;
        l1 = l1 * s1 + rs1;
        m0 = mn0; m1 = mn1;

        // skip O-rescale when no lane saw a new max (x * 1.0f == x exactly)
        if (!__all_sync(0xffffffffu, (s0 == 1.f) && (s1 == 1.f))) {
#pragma unroll
            for (int nt = 0; nt < 13; nt++) {
                of[nt][0] *= s0; of[nt][1] *= s0;
                of[nt][2] *= s1; of[nt][3] *= s1;
            }
        }

        // O += P V
#pragma unroll
        for (int kh = 0; kh < 2; kh++) {
            int ks = kh * 8;
            uint32_t pa[4];
            pa[0] = pp[2 * kh][0];
            pa[1] = pp[2 * kh][1];
            pa[2] = pp[2 * kh + 1][0];
            pa[3] = pp[2 * kh + 1][1];
#pragma unroll
            for (int nt = 0; nt < 13; nt++) {
                uint32_t b0 = v_s[ks + tig][nt * 8 + g];
                uint32_t b1 = v_s[ks + tig + 4][nt * 8 + g];
                MMA_BF16(of[nt], pa, b0, b1);
            }
        }
        __syncthreads();
    }

    size_t pb0 = (size_t)(z * NCH + c) * SQ + r0;
    size_t pb1 = (size_t)(z * NCH + c) * SQ + r1;
#pragma unroll
    for (int nt = 0; nt < 13; nt++) {
        int d = nt * 8 + 2 * tig;
        if (d < HDIM) {
            *(float2*)&part_o[pb0 * HDIM + d] = make_float2(of[nt][0], of[nt][1]);
            *(float2*)&part_o[pb1 * HDIM + d] = make_float2(of[nt][2], of[nt][3]);
        }
    }
    if (tig == 0) {
        part_ml[pb0 * 2] = m0; part_ml[pb0 * 2 + 1] = l0;
        part_ml[pb1 * 2] = m1; part_ml[pb1 * 2 + 1] = l1;
    }
}

__global__ void attn_combine(const float* __restrict__ part_o,
                             const float* __restrict__ part_ml,
                             uint32_t* __restrict__ ob) {
    int qi = blockIdx.x, e = blockIdx.y;
    int t = threadIdx.x, h = threadIdx.y;
    int z = e * 3 + h;
    int nch = qi / JCH + 1;
    float M = -INFINITY;
    for (int cc = 0; cc < nch; cc++)
        M = fmaxf(M, part_ml[((size_t)(z * NCH + cc) * SQ + qi) * 2]);
    float L = 0.f, a0 = 0.f, a1 = 0.f;
    for (int cc = 0; cc < nch; cc++) {
        size_t pb = (size_t)(z * NCH + cc) * SQ + qi;
        float w = __expf(part_ml[pb * 2] - M);
        L += part_ml[pb * 2 + 1] * w;
        if (t < 50) {
            float2 v = *(const float2*)&part_o[pb * HDIM + 2 * t];
            a0 += w * v.x; a1 += w * v.y;
        }
    }
    if (t < 50) {
        float inv = 1.f / L;
        ob[((size_t)e * SQ + qi) * 150 + h * 50 + t] = packbf(a0 * inv, a1 * inv);
    }
}

// ---------------- fused residual + LayerNorm ----------------
__global__ void ln_kernel(float* __restrict__ x, const float* __restrict__ delta,
                          const float* __restrict__ g, const float* __restrict__ b,
                          uint32_t* __restrict__ xb) {
    __shared__ float rs[8];
    int z = blockIdx.z;
    x += (size_t)z * SQ * EMB; delta += (size_t)z * SQ * EMB;
    g += z * EMB; b += z * EMB; xb += (size_t)z * SQ * 150;
    int r = blockIdx.x, t = threadIdx.x;
    int lane = t & 31, wid = t >> 5;
    float v[2][2];
    float s1 = 0.f, s2 = 0.f;
    {
        float2 a = *(const float2*)&x[(size_t)r * EMB + 2 * t];
        float2 d = *(const float2*)&delta[(size_t)r * EMB + 2 * t];
        v[0][0] = a.x + d.x; v[0][1] = a.y + d.y;
        s1 += v[0][0] + v[0][1];
        s2 += v[0][0] * v[0][0] + v[0][1] * v[0][1];
    }
    if (t < 22) {
        int p = t + 128;
        float2 a = *(const float2*)&x[(size_t)r * EMB + 2 * p];
        float2 d = *(const float2*)&delta[(size_t)r * EMB + 2 * p];
        v[1][0] = a.x + d.x; v[1][1] = a.y + d.y;
        s1 += v[1][0] + v[1][1];
        s2 += v[1][0] * v[1][0] + v[1][1] * v[1][1];
    }
#pragma unroll
    for (int off = 16; off > 0; off >>= 1) {
        s1 += __shfl_xor_sync(0xffffffffu, s1, off);
        s2 += __shfl_xor_sync(0xffffffffu, s2, off);
    }
    if (lane == 0) { rs[wid * 2] = s1; rs[wid * 2 + 1] = s2; }
    __syncthreads();
    float S1 = rs[0] + rs[2] + rs[4] + rs[6];
    float S2 = rs[1] + rs[3] + rs[5] + rs[7];
    float mu = S1 / (float)EMB;
    float var = S2 / (float)EMB - mu * mu;
    float rstd = rsqrtf(var + 1e-5f);
    {
        int c = 2 * t;
        float n0 = (v[0][0] - mu) * rstd * g[c] + b[c];
        float n1 = (v[0][1] - mu) * rstd * g[c + 1] + b[c + 1];
        *(float2*)&x[(size_t)r * EMB + c] = make_float2(n0, n1);
        xb[(size_t)r * 150 + t] = packbf(n0, n1);
    }
    if (t < 22) {
        int c = 2 * (t + 128);
        float n0 = (v[1][0] - mu) * rstd * g[c] + b[c];
        float n1 = (v[1][1] - mu) * rstd * g[c + 1] + b[c + 1];
        *(float2*)&x[(size_t)r * EMB + c] = make_float2(n0, n1);
        xb[(size_t)r * 150 + t + 128] = packbf(n0, n1);
    }
}

// ---------------- row softmax over A: fp32 in, bf16 out ----------------
__global__ void softmax_rows(const float* __restrict__ A, __nv_bfloat16* __restrict__ Ab) {
    __shared__ float row[SQ];
    __shared__ float red[256];
    int r = blockIdx.x, t = threadIdx.x;
    float mx = -INFINITY;
    for (int j = t; j < SQ; j += 256) { float v = A[(size_t)r * SQ + j]; row[j] = v; mx = fmaxf(mx, v); }
    red[t] = mx; __syncthreads();
    for (int off = 128; off > 0; off >>= 1) { if (t < off) red[t] = fmaxf(red[t], red[t + off]); __syncthreads(); }
    mx = red[0];
    __syncthreads();
    float s = 0.f;
    for (int j = t; j < SQ; j += 256) { float e = __expf(row[j] - mx); row[j] = e; s += e; }
    red[t] = s; __syncthreads();
    for (int off = 128; off > 0; off >>= 1) { if (t < off) red[t] += red[t + off]; __syncthreads(); }
    float inv = 1.f / red[0];
    uint32_t* out = (uint32_t*)(Ab + (size_t)r * SQ);
    for (int j = 2 * t; j < SQ; j += 512)
        out[j >> 1] = packbf(row[j] * inv, row[j + 1] * inv);
}

// ---------------- coalesced colsum of elementwise max ----------------
__global__ void colsum_partial(const float* __restrict__ H, const float* __restrict__ P,
                               const float* __restrict__ G, const float* __restrict__ Q,
                               float* __restrict__ part) {
    int chunk = blockIdx.x, pair = blockIdx.y;
    int c = threadIdx.x;
    const float* X = pair ? G : H;
    const float* Y = pair ? Q : P;
    int r0 = chunk * 128;
    float s = 0.f;
    for (int r = r0; r < r0 + 128; r++)
        s += fmaxf(X[(size_t)r * EMB + c], Y[(size_t)r * EMB + c]);
    part[((size_t)pair * 32 + chunk) * EMB + c] = s;
}
__global__ void colsum_final(const float* __restrict__ part, float* __restrict__ suv) {
    int j = threadIdx.x;
    int pair = j / EMB, c = j - pair * EMB;
    float s = 0.f;
#pragma unroll
    for (int ch = 0; ch < 32; ch++)
        s += part[((size_t)pair * 32 + ch) * EMB + c];
    suv[j] = s;
}

// ---------------- tiny FC layers ----------------
__global__ void fc1_kernel(const float* __restrict__ inp, const float* __restrict__ w,
                           const float* __restrict__ b, float* __restrict__ out) {
    __shared__ float red[128];
    int i = blockIdx.x, t = threadIdx.x;
    float s = 0.f;
    for (int j = t; j < 2 * EMB; j += 128) s += inp[j] * w[(size_t)i * 2 * EMB + j];
    red[t] = s; __syncthreads();
    for (int off = 64; off > 0; off >>= 1) { if (t < off) red[t] += red[t + off]; __syncthreads(); }
    if (t == 0) out[i] = fmaxf(red[0] + b[i], 0.f);
}

__global__ void fc2_kernel(const float* __restrict__ inp, const float* __restrict__ w,
                           const float* __restrict__ b, float* __restrict__ out) {
    __shared__ float red[256];
    int t = threadIdx.x;
    float s = 0.f;
    for (int j = t; j < EMB; j += 256) s += inp[j] * w[j];
    red[t] = s; __syncthreads();
    for (int off = 128; off > 0; off >>= 1) { if (t < off) red[t] += red[t + off]; __syncthreads(); }
    if (t == 0) out[0] = red[0] + b[0];
}

// ---------------- host orchestration ----------------
extern "C" void kernel_launch(void* const* d_in, const int* in_sizes, int n_in,
                              void* d_out, int out_size) {
    const float* solv = (const float*)d_in[0];
    const float* solu = (const float*)d_in[1];
    const float* ipw  = (const float*)d_in[2];
    const float* ipb  = (const float*)d_in[3];
    const float* ow   = (const float*)d_in[4];
    const float* ob_b = (const float*)d_in[5];
    const float* g1   = (const float*)d_in[6];
    const float* b1   = (const float*)d_in[7];
    const float* w1   = (const float*)d_in[8];
    const float* bb1  = (const float*)d_in[9];
    const float* w2   = (const float*)d_in[10];
    const float* bb2  = (const float*)d_in[11];
    const float* g2   = (const float*)d_in[12];
    const float* b2   = (const float*)d_in[13];
    const float* fc1w = (const float*)d_in[14];
    const float* fc1b = (const float*)d_in[15];
    const float* fc2w = (const float*)d_in[16];
    const float* fc2b = (const float*)d_in[17];

    float *x, *t1, *A, *P, *Q, *Pp, *Qp, *po, *pml, *cpart, *suv, *fc1o;
    uint32_t *xb, *xbT, *wp, *qkvb, *ob, *ffb;
    __nv_bfloat16* Ab;
    cudaGetSymbolAddress((void**)&x,    g_x);
    cudaGetSymbolAddress((void**)&xb,   g_xb);
    cudaGetSymbolAddress((void**)&xbT,  g_xbT);
    cudaGetSymbolAddress((void**)&wp,   g_wpack);
    cudaGetSymbolAddress((void**)&qkvb, g_qkvb);
    cudaGetSymbolAddress((void**)&ob,   g_ob);
    cudaGetSymbolAddress((void**)&t1,   g_t1);
    cudaGetSymbolAddress((void**)&ffb,  g_ffb);
    cudaGetSymbolAddress((void**)&A,    g_A);
    cudaGetSymbolAddress((void**)&Ab,   g_Ab);
    cudaGetSymbolAddress((void**)&P,    g_P);
    cudaGetSymbolAddress((void**)&Q,    g_Q);
    cudaGetSymbolAddress((void**)&Pp,   g_Pp);
    cudaGetSymbolAddress((void**)&Qp,   g_Qp);
    cudaGetSymbolAddress((void**)&po,   g_part_o);
    cudaGetSymbolAddress((void**)&pml,  g_part_ml);
    cudaGetSymbolAddress((void**)&cpart, g_colpart);
    cudaGetSymbolAddress((void**)&suv,  g_suv);
    cudaGetSymbolAddress((void**)&fc1o, g_fc1o);

    const size_t SE = (size_t)SQ * EMB;
    uint32_t* ipwb = wp;
    uint32_t* owb  = wp + 270000;
    uint32_t* w1b  = wp + 360000;
    uint32_t* w2b  = wp + 420000;

    pack4<<<(480000 + 255) / 256, 256>>>(ipw, ow, w1, w2, wp);

    add_pe_kernel<<<dim3((SQ * 150 + 255) / 256, 1, 2), 256>>>(solv, solu, x, xb);

    mma2<0, 0, 0, 2><<<dim3(15, 32, 2), 256>>>(
        (const __nv_bfloat16*)xb, (const __nv_bfloat16*)ipwb, ipb, (float*)qkvb,
        SQ, 3 * EMB, EMB, EMB, EMB,
        (size_t)SQ * EMB, (size_t)3 * EMB * EMB, 3 * EMB, (size_t)SQ * QKVS, 0);

    attn_mma_kernel<<<dim3(SQ / QB, NCH, 6), 128>>>(qkvb, po, pml);
    attn_combine<<<dim3(SQ, 2), dim3(64, 3)>>>(po, pml, ob);

    mma2<0, 0, 0, 0><<<dim3(5, 32, 2), 256>>>(
        (const __nv_bfloat16*)ob, (const __nv_bfloat16*)owb, ob_b, t1,
        SQ, EMB, EMB, EMB, EMB,
        (size_t)SQ * EMB, (size_t)EMB * EMB, EMB, SE, 0);
    ln_kernel<<<dim3(SQ, 1, 2), 128>>>(x, t1, g1, b1, xb);

    mma2<0, 1, 0, 1><<<dim3(4, 32, 2), 256>>>(
        (const __nv_bfloat16*)xb, (const __nv_bfloat16*)w1b, bb1, (float*)ffb,
        SQ, NHID, EMB, EMB, EMB,
        (size_t)SQ * EMB, (size_t)NHID * EMB, NHID, (size_t)SQ * 100, 0);
    mma2<0, 0, 0, 0><<<dim3(5, 32, 2), 256>>>(
        (const __nv_bfloat16*)ffb, (const __nv_bfloat16*)w2b, bb2, t1,
        SQ, EMB, NHID, NHID, NHID,
        (size_t)SQ * NHID, (size_t)EMB * NHID, EMB, SE, 0);
    ln_kernel<<<dim3(SQ, 1, 2), 128>>>(x, t1, g2, b2, xb);

    float* H = x;
    float* G = x + SE;
    uint32_t* Hb = xb;
    uint32_t* Gb = xb + (size_t)SQ * 150;

    transpose_pack<<<dim3(SQ / 64, 5, 2), 256>>>(x, xbT);
    const __nv_bfloat16* HbT = (const __nv_bfloat16*)xbT;
    const __nv_bfloat16* GbT = (const __nv_bfloat16*)xbT + (size_t)EMB * SQ;

    mma2<0, 0, 0, 0><<<dim3(64, 32, 1), 256>>>(
        (const __nv_bfloat16*)Hb, (const __nv_bfloat16*)Gb, (const float*)nullptr, A,
        SQ, SQ, EMB, EMB, EMB, 0, 0, 0, 0, 0);
    softmax_rows<<<SQ, 256>>>(A, Ab);

    mma2_pq<<<dim3(5, 32, 2 * NCH), 256>>>(Ab, GbT, HbT, Pp, Qp);
    reduce_pq<<<dim3((SQ * EMB / 4 + 255) / 256, 2), 256>>>(Pp, Qp, P, Q);

    colsum_partial<<<dim3(32, 2), 300>>>(H, P, G, Q, cpart);
    colsum_final<<<1, 600>>>(cpart, suv);

    fc1_kernel<<<EMB, 128>>>(suv, fc1w, fc1b, fc1o);
    fc2_kernel<<<1, 256>>>(fc1o, fc2w, fc2b, (float*)d_out);
}

// round 16
// speedup vs baseline: 1.0939x; 1.0450x over previous
#include <cuda_runtime.h>
#include <cuda_bf16.h>
#include <math.h>
#include <stdint.h>

#define SQ   4096
#define EMB  300
#define NH   3
#define HDIM 100
#define NHID 200
#define QB   64
#define TJ   32
#define JCH  1024
#define NCH  4
#define KSPL 1024
#define ASTR 136
#define BSTR 72
#define QKVS 468   // padded qkv row stride (words): 3 segs x 156, head stride 52

// ---------------- scratch ----------------
__device__ float g_x[2 * SQ * EMB];
__device__ uint32_t g_xb[2 * SQ * 150];
__device__ uint32_t g_xbT[2 * EMB * (SQ / 2)];
__device__ uint32_t g_wpack[480000];
__device__ __align__(16) uint32_t g_qkvb[2 * SQ * QKVS];
__device__ uint32_t g_ob[2 * SQ * 150];
__device__ float g_t1[2 * SQ * EMB];
__device__ uint32_t g_ffb[2 * SQ * 100];
__device__ float g_A[SQ * SQ];
__device__ __nv_bfloat16 g_Ab[SQ * SQ];
__device__ float g_P[SQ * EMB];
__device__ float g_Q[SQ * EMB];
__device__ float g_Pp[NCH * SQ * EMB];
__device__ float g_Qp[NCH * SQ * EMB];
__device__ float g_part_o[6 * NCH * SQ * HDIM];
__device__ float g_part_ml[6 * NCH * SQ * 2];
__device__ float g_colpart[2 * 32 * EMB];
__device__ float g_suv[2 * EMB];
__device__ float g_fc1o[EMB];

// ---------------- bf16 helpers ----------------
__device__ __forceinline__ uint32_t packbf(float lo, float hi) {
    uint32_t r;
    asm("cvt.rn.bf16x2.f32 %0, %1, %2;" : "=r"(r) : "f"(hi), "f"(lo));
    return r;
}

#define MMA_BF16(C, A, B0, B1)                                                  \
    asm volatile(                                                               \
        "mma.sync.aligned.m16n8k16.row.col.f32.bf16.bf16.f32 "                  \
        "{%0,%1,%2,%3},{%4,%5,%6,%7},{%8,%9},{%0,%1,%2,%3};"                    \
        : "+f"((C)[0]), "+f"((C)[1]), "+f"((C)[2]), "+f"((C)[3])                \
        : "r"((A)[0]), "r"((A)[1]), "r"((A)[2]), "r"((A)[3]), "r"(B0), "r"(B1))

#define LDMX4(R, ADDR)                                                          \
    asm volatile("ldmatrix.sync.aligned.m8n8.x4.shared.b16 {%0,%1,%2,%3}, [%4];" \
        : "=r"((R)[0]), "=r"((R)[1]), "=r"((R)[2]), "=r"((R)[3]) : "r"(ADDR))

// ---------------- packing kernels ----------------
__global__ void pack4(const float* __restrict__ ipw, const float* __restrict__ ow,
                      const float* __restrict__ w1, const float* __restrict__ w2,
                      uint32_t* __restrict__ dst) {
    int i = blockIdx.x * 256 + threadIdx.x;
    if (i >= 480000) return;
    const float* src;
    int off;
    if (i < 270000)      { src = ipw; off = i; }
    else if (i < 360000) { src = ow;  off = i - 270000; }
    else if (i < 420000) { src = w1;  off = i - 360000; }
    else                 { src = w2;  off = i - 420000; }
    float2 v = ((const float2*)src)[off];
    dst[i] = packbf(v.x, v.y);
}

__global__ void transpose_pack(const float* __restrict__ x, uint32_t* __restrict__ xT) {
    __shared__ float tile[64][65];
    int z = blockIdx.z;
    int s0 = blockIdx.x * 64, c0 = blockIdx.y * 64;
    int t = threadIdx.x;
#pragma unroll
    for (int i = 0; i < 16; i++) {
        int idx = t + i * 256;
        int ls = idx >> 6, lc = idx & 63;
        int c = c0 + lc;
        tile[ls][lc] = (c < EMB) ? x[(size_t)z * SQ * EMB + (size_t)(s0 + ls) * EMB + c] : 0.f;
    }
    __syncthreads();
#pragma unroll
    for (int i = 0; i < 8; i++) {
        int idx = t + i * 256;
        int lc = idx >> 5, lsp = idx & 31;
        int c = c0 + lc;
        if (c < EMB)
            xT[(size_t)z * EMB * (SQ / 2) + (size_t)c * (SQ / 2) + (s0 >> 1) + lsp] =
                packbf(tile[2 * lsp][lc], tile[2 * lsp + 1][lc]);
    }
}

// ---------------- positional encoding + add ----------------
__global__ void add_pe_kernel(const float* __restrict__ solv, const float* __restrict__ solu,
                              float* __restrict__ x, uint32_t* __restrict__ xb) {
    int p = blockIdx.x * blockDim.x + threadIdx.x;
    if (p >= SQ * 150) return;
    int z = blockIdx.z;
    const float* src = z ? solu : solv;
    int s = p / 150, pc = p - s * 150, c = 2 * pc;
    float dv = __expf(-(float)c * (logf(10000.0f) / (float)EMB));
    float arg = (float)s * dv;
    float pe0 = sinf(arg), pe1 = cosf(arg);
    float2 a = *(const float2*)&src[(size_t)s * EMB + c];
    float v0 = a.x + pe0, v1 = a.y + pe1;
    *(float2*)&x[(size_t)z * SQ * EMB + (size_t)s * EMB + c] = make_float2(v0, v1);
    xb[(size_t)z * SQ * 150 + p] = packbf(v0, v1);
}

// ---------------- all-bf16 tensor-core GEMM ----------------
template<int TA, int RELU, int SPLITK, int BF16OUT>
__global__ __launch_bounds__(256, 2)
void mma2(const __nv_bfloat16* __restrict__ A, const __nv_bfloat16* __restrict__ B,
          const float* __restrict__ bias, float* __restrict__ C,
          int M, int N, int K, int lda, int ldb,
          size_t sA, size_t sB, size_t sBias, size_t sC, int kc) {
    int z = blockIdx.z;
    int k_begin = 0, k_end = K;
    if (SPLITK) {
        k_begin = z * kc;
        k_end = min(K, k_begin + kc);
        C += (size_t)z * sC;
    } else {
        A += (size_t)z * sA; B += (size_t)z * sB; C += (size_t)z * sC;
        if (bias) bias += (size_t)z * sBias;
    }
    uint32_t* C32 = (uint32_t*)C;

    __shared__ uint32_t As[2][16][ASTR];
    __shared__ uint32_t Bs[2][16][BSTR];

    int t = threadIdx.x;
    int warp = t >> 5, lane = t & 31;
    int g = lane >> 2, tig = lane & 3;
    int wm = warp & 3, wn = warp >> 2;
    int row0 = blockIdx.y * 128, col0 = blockIdx.x * 64;
    int wr0 = wm * 32, wc0 = wn * 32;

    float acc[2][4][4];
#pragma unroll
    for (int i = 0; i < 2; i++)
#pragma unroll
        for (int j = 0; j < 4; j++)
#pragma unroll
            for (int h = 0; h < 4; h++) acc[i][j][h] = 0.f;

    uint32_t ra[8], rb[4];

    auto loadA = [&](int kt) {
        if (!TA) {
            int m = t >> 1, kq = (t & 1) * 16;
            const uint32_t* Ap = (const uint32_t*)(A + (size_t)(row0 + m) * lda + kt + kq);
            if (kt + kq + 15 < k_end) {
#pragma unroll
                for (int u = 0; u < 8; u++) ra[u] = Ap[u];
            } else {
                const unsigned short* A16 = (const unsigned short*)(A + (size_t)(row0 + m) * lda);
#pragma unroll
                for (int u = 0; u < 8; u++) {
                    int gk = kt + kq + 2 * u;
                    uint32_t lo = (gk < k_end) ? A16[gk] : 0;
                    uint32_t hi = (gk + 1 < k_end) ? A16[gk + 1] : 0;
                    ra[u] = lo | (hi << 16);
                }
            }
        } else {
            int kp = t >> 4, mq = (t & 15) * 8;
            int gk0 = kt + 2 * kp;
            bool ok0 = gk0 < k_end, ok1 = gk0 + 1 < k_end;
            const uint32_t* r0p = (const uint32_t*)(A + (size_t)gk0 * lda + row0 + mq);
            const uint32_t* r1p = (const uint32_t*)(A + (size_t)(gk0 + 1) * lda + row0 + mq);
            if (ok1) {
#pragma unroll
                for (int u = 0; u < 4; u++) {
                    uint32_t w0 = r0p[u], w1 = r1p[u];
                    ra[2 * u]     = __byte_perm(w0, w1, 0x5410);
                    ra[2 * u + 1] = __byte_perm(w0, w1, 0x7632);
                }
            } else {
#pragma unroll
                for (int u = 0; u < 4; u++) {
                    uint32_t w0 = ok0 ? r0p[u] : 0;
                    ra[2 * u]     = __byte_perm(w0, 0u, 0x5410);
                    ra[2 * u + 1] = __byte_perm(w0, 0u, 0x7632);
                }
            }
        }
    };
    auto loadB = [&](int kt) {
        int n = t >> 2, kq = (t & 3) * 8;
        int gn = col0 + n;
        bool okn = gn < N;
        const uint32_t* Bp = (const uint32_t*)(B + (size_t)gn * ldb + kt + kq);
        if (okn && kt + kq + 7 < k_end) {
#pragma unroll
            for (int u = 0; u < 4; u++) rb[u] = Bp[u];
        } else {
            const unsigned short* B16 = (const unsigned short*)(B + (size_t)gn * ldb);
#pragma unroll
            for (int u = 0; u < 4; u++) {
                int gk = kt + kq + 2 * u;
                uint32_t lo = (okn && gk < k_end) ? B16[gk] : 0;
                uint32_t hi = (okn && gk + 1 < k_end) ? B16[gk + 1] : 0;
                rb[u] = lo | (hi << 16);
            }
        }
    };
    auto storeA = [&](int bf) {
        if (!TA) {
            int m = t >> 1, kp0 = (t & 1) * 8;
#pragma unroll
            for (int u = 0; u < 8; u++) As[bf][kp0 + u][m] = ra[u];
        } else {
            int kp = t >> 4, mq = (t & 15) * 8;
#pragma unroll
            for (int u = 0; u < 8; u++) As[bf][kp][mq + u] = ra[u];
        }
    };
    auto storeB = [&](int bf) {
        int n = t >> 2, kp0 = (t & 3) * 4;
#pragma unroll
        for (int u = 0; u < 4; u++) Bs[bf][kp0 + u][n] = rb[u];
    };

    int nk = (k_end - k_begin + 31) >> 5;
    loadA(k_begin); loadB(k_begin);
    storeA(0); storeB(0);
    __syncthreads();

    int buf = 0;
    for (int it = 0; it < nk; it++) {
        if (it + 1 < nk) { loadA(k_begin + (it + 1) * 32); loadB(k_begin + (it + 1) * 32); }
#pragma unroll
        for (int ks = 0; ks < 16; ks += 8) {
            uint32_t a[2][4], b[4][2];
#pragma unroll
            for (int i = 0; i < 2; i++) {
                int mb = wr0 + i * 16;
                a[i][0] = As[buf][ks + tig][mb + g];
                a[i][1] = As[buf][ks + tig][mb + 8 + g];
                a[i][2] = As[buf][ks + tig + 4][mb + g];
                a[i][3] = As[buf][ks + tig + 4][mb + 8 + g];
            }
#pragma unroll
            for (int j = 0; j < 4; j++) {
                int nb = wc0 + j * 8;
                b[j][0] = Bs[buf][ks + tig][nb + g];
                b[j][1] = Bs[buf][ks + tig + 4][nb + g];
            }
#pragma unroll
            for (int i = 0; i < 2; i++)
#pragma unroll
                for (int j = 0; j < 4; j++)
                    MMA_BF16(acc[i][j], a[i], b[j][0], b[j][1]);
        }
        if (it + 1 < nk) {
            storeA(1 - buf); storeB(1 - buf);
            __syncthreads();
            buf ^= 1;
        }
    }

#pragma unroll
    for (int i = 0; i < 2; i++) {
        int r0 = row0 + wr0 + i * 16 + g;
#pragma unroll
        for (int j = 0; j < 4; j++) {
            int cc = col0 + wc0 + j * 8 + tig * 2;
#pragma unroll
            for (int h = 0; h < 2; h++) {
                int gr = r0 + h * 8;
                float v0 = acc[i][j][h * 2], v1 = acc[i][j][h * 2 + 1];
                if (!SPLITK && bias) {
                    if (cc < N) v0 += bias[cc];
                    if (cc + 1 < N) v1 += bias[cc + 1];
                }
                if (RELU) { v0 = fmaxf(v0, 0.f); v1 = fmaxf(v1, 0.f); }
                if (BF16OUT == 2) {
                    if (cc < N) {
                        int seg = cc / 300, rem = cc - seg * 300;
                        int hh = rem / 100, wi = rem - hh * 100;
                        C32[(size_t)gr * QKVS + seg * 156 + hh * 52 + (wi >> 1)] = packbf(v0, v1);
                    }
                } else if (BF16OUT == 1) {
                    if (cc < N)
                        C32[(size_t)gr * (N >> 1) + (cc >> 1)] = packbf(v0, v1);
                } else if (cc + 1 < N) {
                    *(float2*)&C[(size_t)gr * N + cc] = make_float2(v0, v1);
                } else if (cc < N) {
                    C[(size_t)gr * N + cc] = v0;
                }
            }
        }
    }
}

// ---------------- fused P+Q split-K GEMM ----------------
__global__ __launch_bounds__(256, 2)
void mma2_pq(const __nv_bfloat16* __restrict__ Ain, const __nv_bfloat16* __restrict__ BP,
             const __nv_bfloat16* __restrict__ BQ, float* __restrict__ CP,
             float* __restrict__ CQ) {
    int z = blockIdx.z;
    int ta = (z >= NCH) ? 1 : 0;
    int zz = ta ? z - NCH : z;
    int k_begin = zz * KSPL;
    const __nv_bfloat16* B = ta ? BQ : BP;
    float* C = (ta ? CQ : CP) + (size_t)zz * SQ * EMB;
    const int lda = SQ, ldb = SQ, N = EMB;

    __shared__ uint32_t As[2][16][ASTR];
    __shared__ uint32_t Bs[2][16][BSTR];

    int t = threadIdx.x;
    int warp = t >> 5, lane = t & 31;
    int g = lane >> 2, tig = lane & 3;
    int wm = warp & 3, wn = warp >> 2;
    int row0 = blockIdx.y * 128, col0 = blockIdx.x * 64;
    int wr0 = wm * 32, wc0 = wn * 32;

    float acc[2][4][4];
#pragma unroll
    for (int i = 0; i < 2; i++)
#pragma unroll
        for (int j = 0; j < 4; j++)
#pragma unroll
            for (int h = 0; h < 4; h++) acc[i][j][h] = 0.f;

    uint32_t ra[8], rb[4];

    auto loadA = [&](int kt) {
        if (!ta) {
            int m = t >> 1, kq = (t & 1) * 16;
            const uint32_t* Ap = (const uint32_t*)(Ain + (size_t)(row0 + m) * lda + kt + kq);
#pragma unroll
            for (int u = 0; u < 8; u++) ra[u] = Ap[u];
        } else {
            int kp = t >> 4, mq = (t & 15) * 8;
            int gk0 = kt + 2 * kp;
            const uint32_t* r0p = (const uint32_t*)(Ain + (size_t)gk0 * lda + row0 + mq);
            const uint32_t* r1p = (const uint32_t*)(Ain + (size_t)(gk0 + 1) * lda + row0 + mq);
#pragma unroll
            for (int u = 0; u < 4; u++) {
                uint32_t w0 = r0p[u], w1 = r1p[u];
                ra[2 * u]     = __byte_perm(w0, w1, 0x5410);
                ra[2 * u + 1] = __byte_perm(w0, w1, 0x7632);
            }
        }
    };
    auto loadB = [&](int kt) {
        int n = t >> 2, kq = (t & 3) * 8;
        int gn = col0 + n;
        if (gn < N) {
            const uint32_t* Bp = (const uint32_t*)(B + (size_t)gn * ldb + kt + kq);
#pragma unroll
            for (int u = 0; u < 4; u++) rb[u] = Bp[u];
        } else {
#pragma unroll
            for (int u = 0; u < 4; u++) rb[u] = 0u;
        }
    };
    auto storeA = [&](int bf) {
        if (!ta) {
            int m = t >> 1, kp0 = (t & 1) * 8;
#pragma unroll
            for (int u = 0; u < 8; u++) As[bf][kp0 + u][m] = ra[u];
        } else {
            int kp = t >> 4, mq = (t & 15) * 8;
#pragma unroll
            for (int u = 0; u < 8; u++) As[bf][kp][mq + u] = ra[u];
        }
    };
    auto storeB = [&](int bf) {
        int n = t >> 2, kp0 = (t & 3) * 4;
#pragma unroll
        for (int u = 0; u < 4; u++) Bs[bf][kp0 + u][n] = rb[u];
    };

    const int nk = KSPL >> 5;
    loadA(k_begin); loadB(k_begin);
    storeA(0); storeB(0);
    __syncthreads();

    int buf = 0;
    for (int it = 0; it < nk; it++) {
        if (it + 1 < nk) { loadA(k_begin + (it + 1) * 32); loadB(k_begin + (it + 1) * 32); }
#pragma unroll
        for (int ks = 0; ks < 16; ks += 8) {
            uint32_t a[2][4], b[4][2];
#pragma unroll
            for (int i = 0; i < 2; i++) {
                int mb = wr0 + i * 16;
                a[i][0] = As[buf][ks + tig][mb + g];
                a[i][1] = As[buf][ks + tig][mb + 8 + g];
                a[i][2] = As[buf][ks + tig + 4][mb + g];
                a[i][3] = As[buf][ks + tig + 4][mb + 8 + g];
            }
#pragma unroll
            for (int j = 0; j < 4; j++) {
                int nb = wc0 + j * 8;
                b[j][0] = Bs[buf][ks + tig][nb + g];
                b[j][1] = Bs[buf][ks + tig + 4][nb + g];
            }
#pragma unroll
            for (int i = 0; i < 2; i++)
#pragma unroll
                for (int j = 0; j < 4; j++)
                    MMA_BF16(acc[i][j], a[i], b[j][0], b[j][1]);
        }
        if (it + 1 < nk) {
            storeA(1 - buf); storeB(1 - buf);
            __syncthreads();
            buf ^= 1;
        }
    }

#pragma unroll
    for (int i = 0; i < 2; i++) {
        int r0 = row0 + wr0 + i * 16 + g;
#pragma unroll
        for (int j = 0; j < 4; j++) {
            int cc = col0 + wc0 + j * 8 + tig * 2;
#pragma unroll
            for (int h = 0; h < 2; h++) {
                int gr = r0 + h * 8;
                float v0 = acc[i][j][h * 2], v1 = acc[i][j][h * 2 + 1];
                if (cc + 1 < N) {
                    *(float2*)&C[(size_t)gr * N + cc] = make_float2(v0, v1);
                } else if (cc < N) {
                    C[(size_t)gr * N + cc] = v0;
                }
            }
        }
    }
}

// ---------------- split-K reduce ----------------
__global__ void reduce_pq(const float* __restrict__ Pp, const float* __restrict__ Qp,
                          float* __restrict__ P, float* __restrict__ Q) {
    int idx = blockIdx.x * 256 + threadIdx.x;
    if (idx >= SQ * EMB / 4) return;
    const float* src = blockIdx.y ? Qp : Pp;
    float* dst = blockIdx.y ? Q : P;
    float4 r = make_float4(0.f, 0.f, 0.f, 0.f);
#pragma unroll
    for (int c = 0; c < NCH; c++) {
        float4 a = ((const float4*)(src + (size_t)c * SQ * EMB))[idx];
        r.x += a.x; r.y += a.y; r.z += a.z; r.w += a.w;
    }
    ((float4*)dst)[idx] = r;
}

// ---------------- bf16 flash attention (R13 + occupancy 6) ----------------
__global__ __launch_bounds__(128, 6)
void attn_mma_kernel(const uint32_t* __restrict__ qb_all,
                     float* __restrict__ part_o, float* __restrict__ part_ml) {
    __shared__ __align__(16) uint32_t k_s[TJ][60];
    __shared__ __align__(16) uint32_t v_s[16][108];
    __shared__ __align__(16) uint32_t q_s[4][16][60];

    int z = blockIdx.z, e = z / 3, h = z % 3;
    int qt = (int)gridDim.x - 1 - (int)blockIdx.x;
    int q0 = qt * QB;
    int c = blockIdx.y, c0 = c * JCH;
    if (c0 > q0 + QB - 1) return;

    const uint32_t* qb = qb_all + (size_t)e * SQ * QKVS;
    int t = threadIdx.x, w = t >> 5, lane = t & 31;
    int g = lane >> 2, tig = lane & 3;

    int r0 = q0 + w * 16 + g;
    int r1 = r0 + 8;

    // stage Q fragments into smem once
    {
        const uint32_t* q0p = qb + (size_t)r0 * QKVS + h * 52;
        const uint32_t* q1p = qb + (size_t)r1 * QKVS + h * 52;
#pragma unroll
        for (int s = 0; s < 7; s++) {
            int dp0 = s * 8 + tig, dp1 = dp0 + 4;
            q_s[w][g][dp0]     = dp0 < 50 ? q0p[dp0] : 0u;
            q_s[w][g + 8][dp0] = dp0 < 50 ? q1p[dp0] : 0u;
            q_s[w][g][dp1]     = dp1 < 50 ? q0p[dp1] : 0u;
            q_s[w][g + 8][dp1] = dp1 < 50 ? q1p[dp1] : 0u;
        }
    }
    // zero pad columns once
    for (int idx = t; idx < 32 * 6; idx += 128) k_s[idx / 6][50 + idx % 6] = 0u;
    for (int idx = t; idx < 16 * 8; idx += 128) v_s[idx / 8][100 + idx % 8] = 0u;

    uint32_t kbase0, kbase1, qbase;
    {
        int tile = lane >> 3, row = lane & 7;
        int krow = (tile >> 1) * 8 + row;
        int kword = (tile & 1) * 4;
        kbase0 = (uint32_t)__cvta_generic_to_shared(&k_s[krow][kword]);
        kbase1 = (uint32_t)__cvta_generic_to_shared(&k_s[16 + krow][kword]);
        int qrow = ((tile & 1) ? 8 : 0) + row;
        int qword = (tile >> 1) * 4;
        qbase = (uint32_t)__cvta_generic_to_shared(&q_s[w][qrow][qword]);
    }

    float of[13][4];
#pragma unroll
    for (int nt = 0; nt < 13; nt++) { of[nt][0] = of[nt][1] = of[nt][2] = of[nt][3] = 0.f; }
    float m0 = -INFINITY, m1 = -INFINITY, l0 = 0.f, l1 = 0.f;

    int jend = min(c0 + JCH, q0 + QB);
    for (int jt = c0; jt < jend; jt += TJ) {
        // K stage: vectorized
        for (int idx = t; idx < 32 * 13; idx += 128) {
            int row = idx / 13, sl = idx - row * 13;
            const uint32_t* src = qb + (size_t)(jt + row) * QKVS + 156 + h * 52;
            if (sl < 12) {
                *(uint4*)&k_s[row][4 * sl] = *(const uint4*)(src + 4 * sl);
            } else {
                *(uint2*)&k_s[row][48] = *(const uint2*)(src + 48);
            }
        }
        // V stage: interleave two j rows, vectorized
        for (int idx = t; idx < 16 * 13; idx += 128) {
            int jp = idx / 13, sl = idx - jp * 13;
            const uint32_t* s0p = qb + (size_t)(jt + 2 * jp) * QKVS + 312 + h * 52;
            const uint32_t* s1p = s0p + QKVS;
            if (sl < 12) {
                uint4 a = *(const uint4*)(s0p + 4 * sl);
                uint4 b = *(const uint4*)(s1p + 4 * sl);
                uint4 o0, o1;
                o0.x = __byte_perm(a.x, b.x, 0x5410); o0.y = __byte_perm(a.x, b.x, 0x7632);
                o0.z = __byte_perm(a.y, b.y, 0x5410); o0.w = __byte_perm(a.y, b.y, 0x7632);
                o1.x = __byte_perm(a.z, b.z, 0x5410); o1.y = __byte_perm(a.z, b.z, 0x7632);
                o1.z = __byte_perm(a.w, b.w, 0x5410); o1.w = __byte_perm(a.w, b.w, 0x7632);
                *(uint4*)&v_s[jp][8 * sl] = o0;
                *(uint4*)&v_s[jp][8 * sl + 4] = o1;
            } else {
                uint2 a = *(const uint2*)(s0p + 48);
                uint2 b = *(const uint2*)(s1p + 48);
                uint4 o;
                o.x = __byte_perm(a.x, b.x, 0x5410); o.y = __byte_perm(a.x, b.x, 0x7632);
                o.z = __byte_perm(a.y, b.y, 0x5410); o.w = __byte_perm(a.y, b.y, 0x7632);
                *(uint4*)&v_s[jp][96] = o;
            }
        }
        __syncthreads();

        // S = Q K^T via ldmatrix fragments
        float sc[4][4];
#pragma unroll
        for (int nt = 0; nt < 4; nt++) { sc[nt][0] = sc[nt][1] = sc[nt][2] = sc[nt][3] = 0.f; }
#pragma unroll
        for (int s = 0; s < 7; s++) {
            uint32_t qa[4], kb0[4], kb1[4];
            LDMX4(qa, qbase + s * 32);
            LDMX4(kb0, kbase0 + s * 32);
            LDMX4(kb1, kbase1 + s * 32);
            MMA_BF16(sc[0], qa, kb0[0], kb0[1]);
            MMA_BF16(sc[1], qa, kb0[2], kb0[3]);
            MMA_BF16(sc[2], qa, kb1[0], kb1[1]);
            MMA_BF16(sc[3], qa, kb1[2], kb1[3]);
        }
#pragma unroll
        for (int nt = 0; nt < 4; nt++) {
            sc[nt][0] *= 0.1f; sc[nt][1] *= 0.1f; sc[nt][2] *= 0.1f; sc[nt][3] *= 0.1f;
        }

        if (jt + TJ > q0) {
#pragma unroll
            for (int nt = 0; nt < 4; nt++) {
                int jb = jt + nt * 8 + 2 * tig;
                if (jb > r0)     sc[nt][0] = -INFINITY;
                if (jb + 1 > r0) sc[nt][1] = -INFINITY;
                if (jb > r1)     sc[nt][2] = -INFINITY;
                if (jb + 1 > r1) sc[nt][3] = -INFINITY;
            }
        }

        float rm0 = -INFINITY, rm1 = -INFINITY;
#pragma unroll
        for (int nt = 0; nt < 4; nt++) {
            rm0 = fmaxf(rm0, fmaxf(sc[nt][0], sc[nt][1]));
            rm1 = fmaxf(rm1, fmaxf(sc[nt][2], sc[nt][3]));
        }
        rm0 = fmaxf(rm0, __shfl_xor_sync(0xffffffffu, rm0, 1));
        rm0 = fmaxf(rm0, __shfl_xor_sync(0xffffffffu, rm0, 2));
        rm1 = fmaxf(rm1, __shfl_xor_sync(0xffffffffu, rm1, 1));
        rm1 = fmaxf(rm1, __shfl_xor_sync(0xffffffffu, rm1, 2));
        float mn0 = fmaxf(m0, rm0), mn1 = fmaxf(m1, rm1);
        float s0 = __expf(m0 - mn0), s1 = __expf(m1 - mn1);

        uint32_t pp[4][2];
        float rs0 = 0.f, rs1 = 0.f;
#pragma unroll
        for (int nt = 0; nt < 4; nt++) {
            float p0 = __expf(sc[nt][0] - mn0);
            float p1 = __expf(sc[nt][1] - mn0);
            float p2 = __expf(sc[nt][2] - mn1);
            float p3 = __expf(sc[nt][3] - mn1);
            rs0 += p0 + p1;
            rs1 += p2 + p3;
            pp[nt][0] = packbf(p0, p1);
            pp[nt][1] = packbf(p2, p3);
        }
        rs0 += __shfl_xor_sync(0xffffffffu, rs0, 1);
        rs0 += __shfl_xor_sync(0xffffffffu, rs0, 2);
        rs1 += __shfl_xor_sync(0xffffffffu, rs1, 1);
        rs1 += __shfl_xor_sync(0xffffffffu, rs1, 2);
        l0 = l0 * s0 + rs0;
        l1 = l1 * s1 + rs1;
        m0 = mn0; m1 = mn1;

#pragma unroll
        for (int nt = 0; nt < 13; nt++) {
            of[nt][0] *= s0; of[nt][1] *= s0;
            of[nt][2] *= s1; of[nt][3] *= s1;
        }

        // O += P V
#pragma unroll
        for (int kh = 0; kh < 2; kh++) {
            int ks = kh * 8;
            uint32_t pa[4];
            pa[0] = pp[2 * kh][0];
            pa[1] = pp[2 * kh][1];
            pa[2] = pp[2 * kh + 1][0];
            pa[3] = pp[2 * kh + 1][1];
#pragma unroll
            for (int nt = 0; nt < 13; nt++) {
                uint32_t b0 = v_s[ks + tig][nt * 8 + g];
                uint32_t b1 = v_s[ks + tig + 4][nt * 8 + g];
                MMA_BF16(of[nt], pa, b0, b1);
            }
        }
        __syncthreads();
    }

    size_t pb0 = (size_t)(z * NCH + c) * SQ + r0;
    size_t pb1 = (size_t)(z * NCH + c) * SQ + r1;
#pragma unroll
    for (int nt = 0; nt < 13; nt++) {
        int d = nt * 8 + 2 * tig;
        if (d < HDIM) {
            *(float2*)&part_o[pb0 * HDIM + d] = make_float2(of[nt][0], of[nt][1]);
            *(float2*)&part_o[pb1 * HDIM + d] = make_float2(of[nt][2], of[nt][3]);
        }
    }
    if (tig == 0) {
        part_ml[pb0 * 2] = m0; part_ml[pb0 * 2 + 1] = l0;
        part_ml[pb1 * 2] = m1; part_ml[pb1 * 2 + 1] = l1;
    }
}

__global__ void attn_combine(const float* __restrict__ part_o,
                             const float* __restrict__ part_ml,
                             uint32_t* __restrict__ ob) {
    int qi = blockIdx.x, e = blockIdx.y;
    int t = threadIdx.x, h = threadIdx.y;
    int z = e * 3 + h;
    int nch = qi / JCH + 1;
    float M = -INFINITY;
    for (int cc = 0; cc < nch; cc++)
        M = fmaxf(M, part_ml[((size_t)(z * NCH + cc) * SQ + qi) * 2]);
    float L = 0.f, a0 = 0.f, a1 = 0.f;
    for (int cc = 0; cc < nch; cc++) {
        size_t pb = (size_t)(z * NCH + cc) * SQ + qi;
        float w = __expf(part_ml[pb * 2] - M);
        L += part_ml[pb * 2 + 1] * w;
        if (t < 50) {
            float2 v = *(const float2*)&part_o[pb * HDIM + 2 * t];
            a0 += w * v.x; a1 += w * v.y;
        }
    }
    if (t < 50) {
        float inv = 1.f / L;
        ob[((size_t)e * SQ + qi) * 150 + h * 50 + t] = packbf(a0 * inv, a1 * inv);
    }
}

// ---------------- fused residual + LayerNorm ----------------
__global__ void ln_kernel(float* __restrict__ x, const float* __restrict__ delta,
                          const float* __restrict__ g, const float* __restrict__ b,
                          uint32_t* __restrict__ xb) {
    __shared__ float rs[8];
    int z = blockIdx.z;
    x += (size_t)z * SQ * EMB; delta += (size_t)z * SQ * EMB;
    g += z * EMB; b += z * EMB; xb += (size_t)z * SQ * 150;
    int r = blockIdx.x, t = threadIdx.x;
    int lane = t & 31, wid = t >> 5;
    float v[2][2];
    float s1 = 0.f, s2 = 0.f;
    {
        float2 a = *(const float2*)&x[(size_t)r * EMB + 2 * t];
        float2 d = *(const float2*)&delta[(size_t)r * EMB + 2 * t];
        v[0][0] = a.x + d.x; v[0][1] = a.y + d.y;
        s1 += v[0][0] + v[0][1];
        s2 += v[0][0] * v[0][0] + v[0][1] * v[0][1];
    }
    if (t < 22) {
        int p = t + 128;
        float2 a = *(const float2*)&x[(size_t)r * EMB + 2 * p];
        float2 d = *(const float2*)&delta[(size_t)r * EMB + 2 * p];
        v[1][0] = a.x + d.x; v[1][1] = a.y + d.y;
        s1 += v[1][0] + v[1][1];
        s2 += v[1][0] * v[1][0] + v[1][1] * v[1][1];
    }
#pragma unroll
    for (int off = 16; off > 0; off >>= 1) {
        s1 += __shfl_xor_sync(0xffffffffu, s1, off);
        s2 += __shfl_xor_sync(0xffffffffu, s2, off);
    }
    if (lane == 0) { rs[wid * 2] = s1; rs[wid * 2 + 1] = s2; }
    __syncthreads();
    float S1 = rs[0] + rs[2] + rs[4] + rs[6];
    float S2 = rs[1] + rs[3] + rs[5] + rs[7];
    float mu = S1 / (float)EMB;
    float var = S2 / (float)EMB - mu * mu;
    float rstd = rsqrtf(var + 1e-5f);
    {
        int c = 2 * t;
        float n0 = (v[0][0] - mu) * rstd * g[c] + b[c];
        float n1 = (v[0][1] - mu) * rstd * g[c + 1] + b[c + 1];
        *(float2*)&x[(size_t)r * EMB + c] = make_float2(n0, n1);
        xb[(size_t)r * 150 + t] = packbf(n0, n1);
    }
    if (t < 22) {
        int c = 2 * (t + 128);
        float n0 = (v[1][0] - mu) * rstd * g[c] + b[c];
        float n1 = (v[1][1] - mu) * rstd * g[c + 1] + b[c + 1];
        *(float2*)&x[(size_t)r * EMB + c] = make_float2(n0, n1);
        xb[(size_t)r * 150 + t + 128] = packbf(n0, n1);
    }
}

// ---------------- row softmax over A: fp32 in, bf16 out ----------------
__global__ void softmax_rows(const float* __restrict__ A, __nv_bfloat16* __restrict__ Ab) {
    __shared__ float row[SQ];
    __shared__ float red[256];
    int r = blockIdx.x, t = threadIdx.x;
    float mx = -INFINITY;
    for (int j = t; j < SQ; j += 256) { float v = A[(size_t)r * SQ + j]; row[j] = v; mx = fmaxf(mx, v); }
    red[t] = mx; __syncthreads();
    for (int off = 128; off > 0; off >>= 1) { if (t < off) red[t] = fmaxf(red[t], red[t + off]); __syncthreads(); }
    mx = red[0];
    __syncthreads();
    float s = 0.f;
    for (int j = t; j < SQ; j += 256) { float e = __expf(row[j] - mx); row[j] = e; s += e; }
    red[t] = s; __syncthreads();
    for (int off = 128; off > 0; off >>= 1) { if (t < off) red[t] += red[t + off]; __syncthreads(); }
    float inv = 1.f / red[0];
    uint32_t* out = (uint32_t*)(Ab + (size_t)r * SQ);
    for (int j = 2 * t; j < SQ; j += 512)
        out[j >> 1] = packbf(row[j] * inv, row[j + 1] * inv);
}

// ---------------- coalesced colsum of elementwise max ----------------
__global__ void colsum_partial(const float* __restrict__ H, const float* __restrict__ P,
                               const float* __restrict__ G, const float* __restrict__ Q,
                               float* __restrict__ part) {
    int chunk = blockIdx.x, pair = blockIdx.y;
    int c = threadIdx.x;
    const float* X = pair ? G : H;
    const float* Y = pair ? Q : P;
    int r0 = chunk * 128;
    float s = 0.f;
    for (int r = r0; r < r0 + 128; r++)
        s += fmaxf(X[(size_t)r * EMB + c], Y[(size_t)r * EMB + c]);
    part[((size_t)pair * 32 + chunk) * EMB + c] = s;
}
__global__ void colsum_final(const float* __restrict__ part, float* __restrict__ suv) {
    int j = threadIdx.x;
    int pair = j / EMB, c = j - pair * EMB;
    float s = 0.f;
#pragma unroll
    for (int ch = 0; ch < 32; ch++)
        s += part[((size_t)pair * 32 + ch) * EMB + c];
    suv[j] = s;
}

// ---------------- tiny FC layers ----------------
__global__ void fc1_kernel(const float* __restrict__ inp, const float* __restrict__ w,
                           const float* __restrict__ b, float* __restrict__ out) {
    __shared__ float red[128];
    int i = blockIdx.x, t = threadIdx.x;
    float s = 0.f;
    for (int j = t; j < 2 * EMB; j += 128) s += inp[j] * w[(size_t)i * 2 * EMB + j];
    red[t] = s; __syncthreads();
    for (int off = 64; off > 0; off >>= 1) { if (t < off) red[t] += red[t + off]; __syncthreads(); }
    if (t == 0) out[i] = fmaxf(red[0] + b[i], 0.f);
}

__global__ void fc2_kernel(const float* __restrict__ inp, const float* __restrict__ w,
                           const float* __restrict__ b, float* __restrict__ out) {
    __shared__ float red[256];
    int t = threadIdx.x;
    float s = 0.f;
    for (int j = t; j < EMB; j += 256) s += inp[j] * w[j];
    red[t] = s; __syncthreads();
    for (int off = 128; off > 0; off >>= 1) { if (t < off) red[t] += red[t + off]; __syncthreads(); }
    if (t == 0) out[0] = red[0] + b[0];
}

// ---------------- host orchestration ----------------
extern "C" void kernel_launch(void* const* d_in, const int* in_sizes, int n_in,
                              void* d_out, int out_size) {
    const float* solv = (const float*)d_in[0];
    const float* solu = (const float*)d_in[1];
    const float* ipw  = (const float*)d_in[2];
    const float* ipb  = (const float*)d_in[3];
    const float* ow   = (const float*)d_in[4];
    const float* ob_b = (const float*)d_in[5];
    const float* g1   = (const float*)d_in[6];
    const float* b1   = (const float*)d_in[7];
    const float* w1   = (const float*)d_in[8];
    const float* bb1  = (const float*)d_in[9];
    const float* w2   = (const float*)d_in[10];
    const float* bb2  = (const float*)d_in[11];
    const float* g2   = (const float*)d_in[12];
    const float* b2   = (const float*)d_in[13];
    const float* fc1w = (const float*)d_in[14];
    const float* fc1b = (const float*)d_in[15];
    const float* fc2w = (const float*)d_in[16];
    const float* fc2b = (const float*)d_in[17];

    float *x, *t1, *A, *P, *Q, *Pp, *Qp, *po, *pml, *cpart, *suv, *fc1o;
    uint32_t *xb, *xbT, *wp, *qkvb, *ob, *ffb;
    __nv_bfloat16* Ab;
    cudaGetSymbolAddress((void**)&x,    g_x);
    cudaGetSymbolAddress((void**)&xb,   g_xb);
    cudaGetSymbolAddress((void**)&xbT,  g_xbT);
    cudaGetSymbolAddress((void**)&wp,   g_wpack);
    cudaGetSymbolAddress((void**)&qkvb, g_qkvb);
    cudaGetSymbolAddress((void**)&ob,   g_ob);
    cudaGetSymbolAddress((void**)&t1,   g_t1);
    cudaGetSymbolAddress((void**)&ffb,  g_ffb);
    cudaGetSymbolAddress((void**)&A,    g_A);
    cudaGetSymbolAddress((void**)&Ab,   g_Ab);
    cudaGetSymbolAddress((void**)&P,    g_P);
    cudaGetSymbolAddress((void**)&Q,    g_Q);
    cudaGetSymbolAddress((void**)&Pp,   g_Pp);
    cudaGetSymbolAddress((void**)&Qp,   g_Qp);
    cudaGetSymbolAddress((void**)&po,   g_part_o);
    cudaGetSymbolAddress((void**)&pml,  g_part_ml);
    cudaGetSymbolAddress((void**)&cpart, g_colpart);
    cudaGetSymbolAddress((void**)&suv,  g_suv);
    cudaGetSymbolAddress((void**)&fc1o, g_fc1o);

    const size_t SE = (size_t)SQ * EMB;
    uint32_t* ipwb = wp;
    uint32_t* owb  = wp + 270000;
    uint32_t* w1b  = wp + 360000;
    uint32_t* w2b  = wp + 420000;

    pack4<<<(480000 + 255) / 256, 256>>>(ipw, ow, w1, w2, wp);

    add_pe_kernel<<<dim3((SQ * 150 + 255) / 256, 1, 2), 256>>>(solv, solu, x, xb);

    mma2<0, 0, 0, 2><<<dim3(15, 32, 2), 256>>>(
        (const __nv_bfloat16*)xb, (const __nv_bfloat16*)ipwb, ipb, (float*)qkvb,
        SQ, 3 * EMB, EMB, EMB, EMB,
        (size_t)SQ * EMB, (size_t)3 * EMB * EMB, 3 * EMB, (size_t)SQ * QKVS, 0);

    attn_mma_kernel<<<dim3(SQ / QB, NCH, 6), 128>>>(qkvb, po, pml);
    attn_combine<<<dim3(SQ, 2), dim3(64, 3)>>>(po, pml, ob);

    mma2<0, 0, 0, 0><<<dim3(5, 32, 2), 256>>>(
        (const __nv_bfloat16*)ob, (const __nv_bfloat16*)owb, ob_b, t1,
        SQ, EMB, EMB, EMB, EMB,
        (size_t)SQ * EMB, (size_t)EMB * EMB, EMB, SE, 0);
    ln_kernel<<<dim3(SQ, 1, 2), 128>>>(x, t1, g1, b1, xb);

    mma2<0, 1, 0, 1><<<dim3(4, 32, 2), 256>>>(
        (const __nv_bfloat16*)xb, (const __nv_bfloat16*)w1b, bb1, (float*)ffb,
        SQ, NHID, EMB, EMB, EMB,
        (size_t)SQ * EMB, (size_t)NHID * EMB, NHID, (size_t)SQ * 100, 0);
    mma2<0, 0, 0, 0><<<dim3(5, 32, 2), 256>>>(
        (const __nv_bfloat16*)ffb, (const __nv_bfloat16*)w2b, bb2, t1,
        SQ, EMB, NHID, NHID, NHID,
        (size_t)SQ * NHID, (size_t)EMB * NHID, EMB, SE, 0);
    ln_kernel<<<dim3(SQ, 1, 2), 128>>>(x, t1, g2, b2, xb);

    float* H = x;
    float* G = x + SE;
    uint32_t* Hb = xb;
    uint32_t* Gb = xb + (size_t)SQ * 150;

    transpose_pack<<<dim3(SQ / 64, 5, 2), 256>>>(x, xbT);
    const __nv_bfloat16* HbT = (const __nv_bfloat16*)xbT;
    const __nv_bfloat16* GbT = (const __nv_bfloat16*)xbT + (size_t)EMB * SQ;

    mma2<0, 0, 0, 0><<<dim3(64, 32, 1), 256>>>(
        (const __nv_bfloat16*)Hb, (const __nv_bfloat16*)Gb, (const float*)nullptr, A,
        SQ, SQ, EMB, EMB, EMB, 0, 0, 0, 0, 0);
    softmax_rows<<<SQ, 256>>>(A, Ab);

    mma2_pq<<<dim3(5, 32, 2 * NCH), 256>>>(Ab, GbT, HbT, Pp, Qp);
    reduce_pq<<<dim3((SQ * EMB / 4 + 255) / 256, 2), 256>>>(Pp, Qp, P, Q);

    colsum_partial<<<dim3(32, 2), 300>>>(H, P, G, Q, cpart);
    colsum_final<<<1, 600>>>(cpart, suv);

    fc1_kernel<<<EMB, 128>>>(suv, fc1w, fc1b, fc1o);
    fc2_kernel<<<1, 256>>>(fc1o, fc2w, fc2b, (float*)d_out);
}